// round 13
// baseline (speedup 1.0000x reference)
#include <cuda_runtime.h>
#include <cstddef>
#include <cstdint>

#define Bz 32
#define Nn 4096
#define Dd 256
#define Kk 8
#define NB 16              // n-chunks per batch in k_attn (256 rows each)

// ---------------- scratch (device globals; no allocations) -----------------
__device__ float  g_slots[Bz * Kk * Dd];
__device__ float  g_q[Bz * Kk * Dd];            // qg = SCALE * q' * ln_in_g
__device__ float  g_qs1[Bz * Kk];               // sum_e qg
__device__ float  g_qb[Bz * Kk];                // SCALE * q' . ln_in_b
__device__ float  g_wqkT[Dd * Dd];              // [f][e] = sum_d Wq[d,e] Wk[d,f]
__device__ float  g_aggp[(size_t)NB * Bz * Kk * Dd];  // partial sum_n (a*rs)*x
__device__ float  g_rsp[NB * Bz * Kk];          // partial sum_n a
__device__ float  g_s2p[NB * Bz * Kk];          // partial sum_n a*m*rs
__device__ float2 g_mr[(size_t)Bz * Nn];        // per emb row: (m*rs, rs)

// ---------------- small helpers ---------------------------------------------
__device__ __forceinline__ void wred2(float& a, float& b) {
#pragma unroll
    for (int o = 16; o > 0; o >>= 1) {
        a += __shfl_xor_sync(0xffffffffu, a, o);
        b += __shfl_xor_sync(0xffffffffu, b, o);
    }
}

__device__ __forceinline__ void cp16(void* dst_smem, const void* src) {
    uint32_t d = (uint32_t)__cvta_generic_to_shared(dst_smem);
    asm volatile("cp.async.ca.shared.global [%0], [%1], 16;" :: "r"(d), "l"(src));
}
__device__ __forceinline__ void cp8(void* dst_smem, const void* src) {
    uint32_t d = (uint32_t)__cvta_generic_to_shared(dst_smem);
    asm volatile("cp.async.ca.shared.global [%0], [%1], 8;" :: "r"(d), "l"(src));
}
#define CP_COMMIT() asm volatile("cp.async.commit_group;")
#define CP_WAIT0()  asm volatile("cp.async.wait_group 0;" ::: "memory")

// LN over one 256-row in smem, one warp per row
__device__ __forceinline__ void ln_row(const float* __restrict__ in,
                                       float* __restrict__ out,
                                       const float* __restrict__ g,
                                       const float* __restrict__ bb, int lane) {
    float4 v1 = *(const float4*)(in + lane * 4);
    float4 v2 = *(const float4*)(in + 128 + lane * 4);
    float s = v1.x + v1.y + v1.z + v1.w + v2.x + v2.y + v2.z + v2.w;
    float ss = v1.x * v1.x + v1.y * v1.y + v1.z * v1.z + v1.w * v1.w
             + v2.x * v2.x + v2.y * v2.y + v2.z * v2.z + v2.w * v2.w;
    wred2(s, ss);
    float m = s * (1.f / 256.f);
    float rs = rsqrtf(ss * (1.f / 256.f) - m * m + 1e-5f);
    int d = lane * 4;
    float4 ga = *(const float4*)(g + d), ba = *(const float4*)(bb + d);
    out[d + 0] = (v1.x - m) * rs * ga.x + ba.x;
    out[d + 1] = (v1.y - m) * rs * ga.y + ba.y;
    out[d + 2] = (v1.z - m) * rs * ga.z + ba.z;
    out[d + 3] = (v1.w - m) * rs * ga.w + ba.w;
    int d2 = d + 128;
    float4 gb = *(const float4*)(g + d2), bbv = *(const float4*)(bb + d2);
    out[d2 + 0] = (v2.x - m) * rs * gb.x + bbv.x;
    out[d2 + 1] = (v2.y - m) * rs * gb.y + bbv.y;
    out[d2 + 2] = (v2.z - m) * rs * gb.z + bbv.z;
    out[d2 + 3] = (v2.w - m) * rs * gb.w + bbv.w;
}

// full-K gemv: acc[r] += W[j,:].src[r][:]  (256 wide, broadcast src from smem)
__device__ __forceinline__ void gemv8_full(const float* __restrict__ W, int j,
                                           const float (*src)[256], float acc[8]) {
    const float4* wr = (const float4*)(W + (size_t)j * 256);
#pragma unroll 8
    for (int c4 = 0; c4 < 64; c4++) {
        float4 w = wr[c4];
#pragma unroll
        for (int r = 0; r < 8; r++) {
            float4 s4 = *(const float4*)&src[r][c4 * 4];
            acc[r] += w.x * s4.x + w.y * s4.y + w.z * s4.z + w.w * s4.w;
        }
    }
}

// half-K gemv (K split over hf = 0/1)
__device__ __forceinline__ void gemv8h(const float* __restrict__ W, int j, int hf,
                                       const float (*src)[256], float acc[8]) {
    const float4* wr = (const float4*)(W + (size_t)j * 256) + hf * 32;
    const float4* s0 = (const float4*)&src[0][0] + hf * 32;
#pragma unroll 8
    for (int c = 0; c < 32; c++) {
        float4 w = wr[c];
#pragma unroll
        for (int r = 0; r < 8; r++) {
            float4 s4 = s0[r * 64 + c];
            acc[r] += w.x * s4.x + w.y * s4.y + w.z * s4.z + w.w * s4.w;
        }
    }
}

__device__ __forceinline__ void gemv8h_dual(const float* __restrict__ Wi,
                                            const float* __restrict__ Wh, int j, int hf,
                                            const float (*u)[256], const float (*h)[256],
                                            float acc[8]) {
    const float4* wi = (const float4*)(Wi + (size_t)j * 256) + hf * 32;
    const float4* wh = (const float4*)(Wh + (size_t)j * 256) + hf * 32;
    const float4* u0 = (const float4*)&u[0][0] + hf * 32;
    const float4* h0 = (const float4*)&h[0][0] + hf * 32;
#pragma unroll 4
    for (int c = 0; c < 32; c++) {
        float4 a = wi[c], d = wh[c];
#pragma unroll
        for (int r = 0; r < 8; r++) {
            float4 uu = u0[r * 64 + c], hh = h0[r * 64 + c];
            acc[r] += a.x * uu.x + a.y * uu.y + a.z * uu.z + a.w * uu.w
                    + d.x * hh.x + d.y * hh.y + d.z * hh.z + d.w * hh.w;
        }
    }
}

__device__ __forceinline__ void gemv8h_dual2(const float* __restrict__ Wi,
                                             const float* __restrict__ Wh, int j, int hf,
                                             const float (*u)[256], const float (*h)[256],
                                             float ai[8], float ah[8]) {
    const float4* wi = (const float4*)(Wi + (size_t)j * 256) + hf * 32;
    const float4* wh = (const float4*)(Wh + (size_t)j * 256) + hf * 32;
    const float4* u0 = (const float4*)&u[0][0] + hf * 32;
    const float4* h0 = (const float4*)&h[0][0] + hf * 32;
#pragma unroll 4
    for (int c = 0; c < 32; c++) {
        float4 a = wi[c], d = wh[c];
#pragma unroll
        for (int r = 0; r < 8; r++) {
            float4 uu = u0[r * 64 + c], hh = h0[r * 64 + c];
            ai[r] += a.x * uu.x + a.y * uu.y + a.z * uu.z + a.w * uu.w;
            ah[r] += d.x * hh.x + d.y * hh.y + d.z * hh.z + d.w * hh.w;
        }
    }
}

// ---------------- one-time kernels -------------------------------------------
__global__ void k_init_slots(const float* __restrict__ noise,
                             const float* __restrict__ mu,
                             const float* __restrict__ ls) {
    int i = blockIdx.x * 256 + threadIdx.x;
    int d = i & 255;
    g_slots[i] = mu[d] + expf(ls[d]) * noise[i];
}

__global__ void __launch_bounds__(256) k_rowstats(const float* __restrict__ emb) {
    int row = blockIdx.x * 8 + (threadIdx.x >> 5);
    int lane = threadIdx.x & 31;
    const float4* er = (const float4*)(emb + (size_t)row * 256);
    float4 v1 = er[lane];
    float4 v2 = er[lane + 32];
    float s = v1.x + v1.y + v1.z + v1.w + v2.x + v2.y + v2.z + v2.w;
    float ss = v1.x * v1.x + v1.y * v1.y + v1.z * v1.z + v1.w * v1.w
             + v2.x * v2.x + v2.y * v2.y + v2.z * v2.z + v2.w * v2.w;
    wred2(s, ss);
    if (lane == 0) {
        float m = s * (1.f / 256.f);
        float rs = rsqrtf(ss * (1.f / 256.f) - m * m + 1e-5f);
        g_mr[row] = make_float2(m * rs, rs);
    }
}

__global__ void __launch_bounds__(256) k_wqk(const float* __restrict__ Wq,
                                             const float* __restrict__ Wk) {
    __shared__ float sq[32][33], sk[32][33];
    int be = blockIdx.x, bf = blockIdx.y, tid = threadIdx.x;
    int dd = tid >> 3, e4 = (tid & 7) * 4;
    int ff = tid & 31, eo = (tid >> 5) * 4;
    float acc[4] = {};
    for (int d0 = 0; d0 < 256; d0 += 32) {
        float4 q4 = *(const float4*)(Wq + (size_t)(d0 + dd) * 256 + be * 32 + e4);
        float4 k4 = *(const float4*)(Wk + (size_t)(d0 + dd) * 256 + bf * 32 + e4);
        sq[dd][e4 + 0] = q4.x; sq[dd][e4 + 1] = q4.y; sq[dd][e4 + 2] = q4.z; sq[dd][e4 + 3] = q4.w;
        sk[dd][e4 + 0] = k4.x; sk[dd][e4 + 1] = k4.y; sk[dd][e4 + 2] = k4.z; sk[dd][e4 + 3] = k4.w;
        __syncthreads();
#pragma unroll
        for (int d = 0; d < 32; d++) {
            float kv = sk[d][ff];
            acc[0] += sq[d][eo + 0] * kv;
            acc[1] += sq[d][eo + 1] * kv;
            acc[2] += sq[d][eo + 2] * kv;
            acc[3] += sq[d][eo + 3] * kv;
        }
        __syncthreads();
    }
    float* o = g_wqkT + (size_t)(bf * 32 + ff) * 256 + be * 32 + eo;
    o[0] = acc[0]; o[1] = acc[1]; o[2] = acc[2]; o[3] = acc[3];
}

// q-prep for iteration 0: qg, qs1, qb from current slots
__global__ void __launch_bounds__(256) k_prep0(const float* __restrict__ lslg,
                                               const float* __restrict__ lslb,
                                               const float* __restrict__ ling,
                                               const float* __restrict__ linb) {
    __shared__ __align__(16) float h[8][256], sn[8][256], qb_s[8][256];
    int b = blockIdx.x, tid = threadIdx.x, warp = tid >> 5, lane = tid & 31;
#pragma unroll
    for (int i = 0; i < 8; i++) {
        int idx = i * 256 + tid; int r = idx >> 8, e = idx & 255;
        h[r][e] = g_slots[(b * 8 + r) * 256 + e];
    }
    __syncthreads();
    ln_row(&h[warp][0], &sn[warp][0], lslg, lslb, lane);
    __syncthreads();
    float acc[8] = {};
    gemv8_full(g_wqkT, tid, sn, acc);
    float gv = ling[tid] * 0.0625f, bv = linb[tid] * 0.0625f;
#pragma unroll
    for (int r = 0; r < 8; r++) {
        float qgv = acc[r] * gv;
        g_q[(b * 8 + r) * 256 + tid] = qgv;
        h[r][tid] = qgv;
        qb_s[r][tid] = acc[r] * bv;
    }
    __syncthreads();
    float s1v = 0.f, s2v = 0.f;
#pragma unroll
    for (int i = 0; i < 8; i++) {
        s1v += h[warp][lane + 32 * i];
        s2v += qb_s[warp][lane + 32 * i];
    }
    wred2(s1v, s2v);
    if (lane == 0) { g_qs1[b * 8 + warp] = s1v; g_qb[b * 8 + warp] = s2v; }
}

// ---------------- streaming attention pass (raw emb, cp.async pipelined) ----
struct AttnSmem {
    float  qg[8][260];
    float  xb[2][32][260];
    float2 mr[2][32];
    float  at4[32][8];
    float  atp[32][8];
    float  rs_s[8][33];
    float  s2_s[8][33];
};

__global__ void __launch_bounds__(256) k_attn(const float* __restrict__ emb,
                                              float* __restrict__ attn_out) {
    extern __shared__ char smem_raw[];
    AttnSmem* S = (AttnSmem*)smem_raw;
    int b = blockIdx.y, nb = blockIdx.x, tid = threadIdx.x;
    int kk = tid & 7, nl = tid >> 3;

    {   // stage qg
        const float4* qsrc = (const float4*)(g_q + b * 8 * 256);
#pragma unroll
        for (int i = 0; i < 2; i++) {
            int p = tid + i * 256; int r = p >> 6, c4 = p & 63;
            *(float4*)&S->qg[r][c4 * 4] = qsrc[p];
        }
    }
    float qs1k = g_qs1[b * 8 + kk], qbk = g_qb[b * 8 + kk];

    const float* esrc = emb + ((size_t)b * Nn + nb * 256) * 256;
    const float2* msrc = g_mr + (size_t)b * Nn + nb * 256;

    auto issue = [&](int t) {
        int buf = t & 1;
        const float* src = esrc + (size_t)t * 32 * 256;
#pragma unroll
        for (int i = 0; i < 8; i++) {
            int p = tid + i * 256; int r = p >> 6, c4 = p & 63;
            cp16(&S->xb[buf][r][c4 * 4], src + r * 256 + c4 * 4);
        }
        if (tid < 32) cp8(&S->mr[buf][tid], msrc + t * 32 + tid);
        CP_COMMIT();
    };

    float aggr[8] = {};
    float rsl = 0.f, s2l = 0.f;
    issue(0);

    for (int t = 0; t < 8; t++) {
        CP_WAIT0();
        __syncthreads();
        if (t < 7) issue(t + 1);
        int buf = t & 1;

        // dots: thread (kk, nl) -- raw x, LN folded into scalars
        float2 mrv = S->mr[buf][nl];
        const float* qr = &S->qg[kk][0];
        const float* xr = &S->xb[buf][nl][0];
        float d0 = 0.f, d1 = 0.f, d2 = 0.f, d3 = 0.f;
#pragma unroll
        for (int c = 0; c < 64; c += 4) {
            float4 q0 = *(const float4*)(qr + c * 4),      x0 = *(const float4*)(xr + c * 4);
            float4 q1 = *(const float4*)(qr + c * 4 + 4),  x1 = *(const float4*)(xr + c * 4 + 4);
            float4 q2 = *(const float4*)(qr + c * 4 + 8),  x2 = *(const float4*)(xr + c * 4 + 8);
            float4 q3 = *(const float4*)(qr + c * 4 + 12), x3 = *(const float4*)(xr + c * 4 + 12);
            d0 += q0.x * x0.x + q0.y * x0.y + q0.z * x0.z + q0.w * x0.w;
            d1 += q1.x * x1.x + q1.y * x1.y + q1.z * x1.z + q1.w * x1.w;
            d2 += q2.x * x2.x + q2.y * x2.y + q2.z * x2.z + q2.w * x2.w;
            d3 += q3.x * x3.x + q3.y * x3.y + q3.z * x3.z + q3.w * x3.w;
        }
        float dval = mrv.y * ((d0 + d1) + (d2 + d3)) - mrv.x * qs1k + qbk;

        // softmax over the 8 slots (lanes xor 1,2,4 share nl)
        float mx = dval;
        mx = fmaxf(mx, __shfl_xor_sync(0xffffffffu, mx, 1));
        mx = fmaxf(mx, __shfl_xor_sync(0xffffffffu, mx, 2));
        mx = fmaxf(mx, __shfl_xor_sync(0xffffffffu, mx, 4));
        float ev = expf(dval - mx);
        float sm = ev;
        sm += __shfl_xor_sync(0xffffffffu, sm, 1);
        sm += __shfl_xor_sync(0xffffffffu, sm, 2);
        sm += __shfl_xor_sync(0xffffffffu, sm, 4);
        float a = ev / sm + 1e-8f;
        rsl += a;
        s2l += a * mrv.x;
        S->at4[nl][kk] = a * mrv.y;
        if (attn_out) S->atp[nl][kk] = a;
        __syncthreads();

        if (attn_out) {
            int k2 = tid >> 5, n2 = tid & 31;
            attn_out[(size_t)(b * 8 + k2) * Nn + nb * 256 + t * 32 + n2] = S->atp[n2][k2];
        }

        // agg' accumulation: thread owns column e = tid
        const float* xcol = &S->xb[buf][0][0];
#pragma unroll 4
        for (int n = 0; n < 32; n++) {
            float xv = xcol[n * 260 + tid];
            float4 a0 = *(const float4*)&S->at4[n][0];
            float4 a1 = *(const float4*)&S->at4[n][4];
            aggr[0] += a0.x * xv; aggr[1] += a0.y * xv;
            aggr[2] += a0.z * xv; aggr[3] += a0.w * xv;
            aggr[4] += a1.x * xv; aggr[5] += a1.y * xv;
            aggr[6] += a1.z * xv; aggr[7] += a1.w * xv;
        }
        // no trailing sync: next iteration's wait+sync orders reuse
    }

    S->rs_s[kk][nl] = rsl;
    S->s2_s[kk][nl] = s2l;
    __syncthreads();
    if (tid < 8) {
        float s = 0.f, s2 = 0.f;
#pragma unroll
        for (int i = 0; i < 32; i++) { s += S->rs_s[tid][i]; s2 += S->s2_s[tid][i]; }
        g_rsp[(nb * Bz + b) * 8 + tid] = s;
        g_s2p[(nb * Bz + b) * 8 + tid] = s2;
    }
    size_t base = (size_t)(nb * Bz + b) * 8 * 256;
#pragma unroll
    for (int k = 0; k < 8; k++) g_aggp[base + k * 256 + tid] = aggr[k];
}

// ---------------- fused: reduce -> upd -> GRU -> LN -> MLP -> next q' -------
struct FusedSmem {
    float ag[8][256], h[8][256], us[8][256], snew[8][256], sn[8][256];
    float ph[2][8][256], phb[2][8][256];
    float s1[8], s2[8], rinv[8];
};

__global__ void __launch_bounds__(512) k_fused(
    const float* __restrict__ Wv,
    const float* __restrict__ W_ih, const float* __restrict__ W_hh,
    const float* __restrict__ b_ih, const float* __restrict__ b_hh,
    const float* __restrict__ W1, const float* __restrict__ b1,
    const float* __restrict__ W2, const float* __restrict__ b2,
    const float* __restrict__ lffg, const float* __restrict__ lffb,
    const float* __restrict__ lslg, const float* __restrict__ lslb,
    const float* __restrict__ ling, const float* __restrict__ linb,
    float* __restrict__ out_slots, int do_prep) {
    extern __shared__ char smem_raw[];
    FusedSmem* S = (FusedSmem*)smem_raw;
    int b = blockIdx.x, tid = threadIdx.x;
    int j = tid & 255, hf = tid >> 8;
    int warp = tid >> 5, lane = tid & 31;

    // stage a: reduce partials, load slots, affine-correct agg
    if (tid < 8) {
        float s1 = 0.f, s2 = 0.f;
#pragma unroll
        for (int nb = 0; nb < NB; nb++) {
            s1 += g_rsp[(nb * Bz + b) * 8 + tid];
            s2 += g_s2p[(nb * Bz + b) * 8 + tid];
        }
        S->s1[tid] = s1; S->s2[tid] = s2; S->rinv[tid] = 1.f / s1;
    }
#pragma unroll
    for (int i = 0; i < 4; i++) {
        int idx = tid + i * 512; int r = idx >> 8, e = idx & 255;
        float a = 0.f;
#pragma unroll
        for (int nb = 0; nb < NB; nb++) a += g_aggp[((size_t)(nb * Bz + b) * 8 + r) * 256 + e];
        S->ag[r][e] = a;
        S->h[r][e] = g_slots[(b * 8 + r) * 256 + e];
    }
    __syncthreads();
#pragma unroll
    for (int i = 0; i < 4; i++) {
        int idx = tid + i * 512; int r = idx >> 8, e = idx & 255;
        S->ag[r][e] = ling[e] * (S->ag[r][e] - S->s2[r]) + linb[e] * S->s1[r];
    }
    __syncthreads();

    // stage b: us = (agg @ Wv^T) / rowsum
    {
        float acc[8] = {};
        gemv8h(Wv, j, hf, S->ag, acc);
#pragma unroll
        for (int r = 0; r < 8; r++) S->ph[hf][r][j] = acc[r];
    }
    __syncthreads();
#pragma unroll
    for (int i = 0; i < 4; i++) {
        int idx = tid + i * 512; int r = idx >> 8, e = idx & 255;
        S->us[r][e] = (S->ph[0][r][e] + S->ph[1][r][e]) * S->rinv[r];
    }
    __syncthreads();

    // stage c: r gate -> ag
    {
        float acc[8] = {};
        gemv8h_dual(W_ih, W_hh, j, hf, S->us, S->h, acc);
#pragma unroll
        for (int r = 0; r < 8; r++) S->ph[hf][r][j] = acc[r];
    }
    __syncthreads();
#pragma unroll
    for (int i = 0; i < 4; i++) {
        int idx = tid + i * 512; int r = idx >> 8, e = idx & 255;
        float v = S->ph[0][r][e] + S->ph[1][r][e] + b_ih[e] + b_hh[e];
        S->ag[r][e] = 1.f / (1.f + expf(-v));
    }
    __syncthreads();

    // stage d: n gate -> sn (temp)
    {
        float ai[8] = {}, ah[8] = {};
        gemv8h_dual2(W_ih + (size_t)512 * 256, W_hh + (size_t)512 * 256, j, hf,
                     S->us, S->h, ai, ah);
#pragma unroll
        for (int r = 0; r < 8; r++) { S->ph[hf][r][j] = ai[r]; S->phb[hf][r][j] = ah[r]; }
    }
    __syncthreads();
#pragma unroll
    for (int i = 0; i < 4; i++) {
        int idx = tid + i * 512; int r = idx >> 8, e = idx & 255;
        float ai = S->ph[0][r][e] + S->ph[1][r][e] + b_ih[512 + e];
        float ah = S->phb[0][r][e] + S->phb[1][r][e] + b_hh[512 + e];
        S->sn[r][e] = tanhf(ai + S->ag[r][e] * ah);
    }
    __syncthreads();

    // stage e: z gate + combine -> snew
    {
        float acc[8] = {};
        gemv8h_dual(W_ih + (size_t)256 * 256, W_hh + (size_t)256 * 256, j, hf,
                    S->us, S->h, acc);
#pragma unroll
        for (int r = 0; r < 8; r++) S->ph[hf][r][j] = acc[r];
    }
    __syncthreads();
#pragma unroll
    for (int i = 0; i < 4; i++) {
        int idx = tid + i * 512; int r = idx >> 8, e = idx & 255;
        float v = S->ph[0][r][e] + S->ph[1][r][e] + b_ih[256 + e] + b_hh[256 + e];
        float z = 1.f / (1.f + expf(-v));
        S->snew[r][e] = (1.f - z) * S->sn[r][e] + z * S->h[r][e];
    }
    __syncthreads();

    // stage f: LN(snew) -> sn
    if (warp < 8) ln_row(&S->snew[warp][0], &S->sn[warp][0], lffg, lffb, lane);
    __syncthreads();

    // stage g: MLP1 -> ag (leaky relu)
    {
        float acc[8] = {};
        gemv8h(W1, j, hf, S->sn, acc);
#pragma unroll
        for (int r = 0; r < 8; r++) S->ph[hf][r][j] = acc[r];
    }
    __syncthreads();
#pragma unroll
    for (int i = 0; i < 4; i++) {
        int idx = tid + i * 512; int r = idx >> 8, e = idx & 255;
        float t = S->ph[0][r][e] + S->ph[1][r][e] + b1[e];
        S->ag[r][e] = (t > 0.f) ? t : 0.01f * t;
    }
    __syncthreads();

    // stage h: MLP2 + residual -> slots (and h for prep)
    {
        float acc[8] = {};
        gemv8h(W2, j, hf, S->ag, acc);
#pragma unroll
        for (int r = 0; r < 8; r++) S->ph[hf][r][j] = acc[r];
    }
    __syncthreads();
#pragma unroll
    for (int i = 0; i < 4; i++) {
        int idx = tid + i * 512; int r = idx >> 8, e = idx & 255;
        float o = S->snew[r][e] + S->ph[0][r][e] + S->ph[1][r][e] + b2[e];
        g_slots[(b * 8 + r) * 256 + e] = o;
        if (out_slots) out_slots[(b * 8 + r) * 256 + e] = o;
        S->h[r][e] = o;
    }
    __syncthreads();

    // stage i: prep next iteration's qg / qs1 / qb
    if (do_prep) {
        if (warp < 8) ln_row(&S->h[warp][0], &S->sn[warp][0], lslg, lslb, lane);
        __syncthreads();
        {
            float acc[8] = {};
            gemv8h(g_wqkT, j, hf, S->sn, acc);
#pragma unroll
            for (int r = 0; r < 8; r++) S->ph[hf][r][j] = acc[r];
        }
        __syncthreads();
#pragma unroll
        for (int i = 0; i < 4; i++) {
            int idx = tid + i * 512; int r = idx >> 8, e = idx & 255;
            float qp = S->ph[0][r][e] + S->ph[1][r][e];
            float qgv = 0.0625f * qp * ling[e];
            g_q[(b * 8 + r) * 256 + e] = qgv;
            S->us[r][e] = qgv;
            S->snew[r][e] = 0.0625f * qp * linb[e];
        }
        __syncthreads();
        if (warp < 8) {
            float s1v = 0.f, s2v = 0.f;
#pragma unroll
            for (int i = 0; i < 8; i++) {
                s1v += S->us[warp][lane + 32 * i];
                s2v += S->snew[warp][lane + 32 * i];
            }
            wred2(s1v, s2v);
            if (lane == 0) { g_qs1[b * 8 + warp] = s1v; g_qb[b * 8 + warp] = s2v; }
        }
    }
}

// ---------------- launch ------------------------------------------------------
extern "C" void kernel_launch(void* const* d_in, const int* in_sizes, int n_in,
                              void* d_out, int out_size) {
    const float* emb   = (const float*)d_in[0];
    const float* noise = (const float*)d_in[1];
    const float* mu    = (const float*)d_in[2];
    const float* ls    = (const float*)d_in[3];
    const float* Wq    = (const float*)d_in[4];
    const float* Wk    = (const float*)d_in[5];
    const float* Wv    = (const float*)d_in[6];
    const float* W_ih  = (const float*)d_in[7];
    const float* W_hh  = (const float*)d_in[8];
    const float* b_ih  = (const float*)d_in[9];
    const float* b_hh  = (const float*)d_in[10];
    const float* W1    = (const float*)d_in[11];
    const float* b1    = (const float*)d_in[12];
    const float* W2    = (const float*)d_in[13];
    const float* b2    = (const float*)d_in[14];
    const float* lin_g = (const float*)d_in[15];
    const float* lin_b = (const float*)d_in[16];
    const float* lsl_g = (const float*)d_in[17];
    const float* lsl_b = (const float*)d_in[18];
    const float* lff_g = (const float*)d_in[19];
    const float* lff_b = (const float*)d_in[20];

    float* out       = (float*)d_out;
    float* out_slots = out;                  // [B,K,D]
    float* out_attn  = out + Bz * Kk * Dd;   // [B,K,N]

    cudaFuncSetAttribute(k_attn, cudaFuncAttributeMaxDynamicSharedMemorySize,
                         (int)sizeof(AttnSmem));
    cudaFuncSetAttribute(k_fused, cudaFuncAttributeMaxDynamicSharedMemorySize,
                         (int)sizeof(FusedSmem));

    k_init_slots<<<(Bz * Kk * Dd) / 256, 256>>>(noise, mu, ls);
    k_rowstats<<<(Bz * Nn) / 8, 256>>>(emb);
    k_wqk<<<dim3(8, 8), 256>>>(Wq, Wk);
    k_prep0<<<Bz, 256>>>(lsl_g, lsl_b, lin_g, lin_b);

    for (int it = 0; it < 3; it++) {
        k_attn<<<dim3(NB, Bz), 256, sizeof(AttnSmem)>>>(
            emb, (it == 2) ? out_attn : nullptr);
        k_fused<<<Bz, 512, sizeof(FusedSmem)>>>(
            Wv, W_ih, W_hh, b_ih, b_hh, W1, b1, W2, b2,
            lff_g, lff_b, lsl_g, lsl_b, lin_g, lin_b,
            (it == 2) ? out_slots : nullptr, (it < 2) ? 1 : 0);
    }
}

// round 14
// speedup vs baseline: 1.8240x; 1.8240x over previous
#include <cuda_runtime.h>
#include <cstddef>
#include <cstdint>

#define Bz 32
#define Nn 4096
#define Dd 256
#define Kk 8
#define NB 16              // n-chunks per batch in k_attn (256 rows each)

// ---------------- scratch (device globals; no allocations) -----------------
__device__ float  g_slots[Bz * Kk * Dd];
__device__ float  g_q[Bz * Kk * Dd];            // qg = SCALE * q' * ln_in_g
__device__ float  g_qs1[Bz * Kk];               // sum_e qg
__device__ float  g_qb[Bz * Kk];                // SCALE * q' . ln_in_b
__device__ float  g_wqk2[Dd * Dd];              // [e][f] = sum_d Wq[d,e] Wk[d,f]
__device__ float  g_aggp[(size_t)NB * Bz * Kk * Dd];  // partial sum_n (a*rs)*x
__device__ float  g_rsp[NB * Bz * Kk];          // partial sum_n a
__device__ float  g_s2p[NB * Bz * Kk];          // partial sum_n a*m*rs
__device__ float2 g_mr[(size_t)Bz * Nn];        // per emb row: (m*rs, rs)
// transposed weights: Wt[k][j] = W[j][k]
__device__ float  g_WvT[Dd * Dd];
__device__ float  g_WihT[Dd * 3 * Dd];          // [256][768]
__device__ float  g_WhhT[Dd * 3 * Dd];          // [256][768]
__device__ float  g_W1T[Dd * Dd];
__device__ float  g_W2T[Dd * Dd];

// ---------------- helpers ----------------------------------------------------
__device__ __forceinline__ void wred2(float& a, float& b) {
#pragma unroll
    for (int o = 16; o > 0; o >>= 1) {
        a += __shfl_xor_sync(0xffffffffu, a, o);
        b += __shfl_xor_sync(0xffffffffu, b, o);
    }
}

// LN over one 256-row in smem, one warp per row
__device__ __forceinline__ void ln_row(const float* __restrict__ in,
                                       float* __restrict__ out,
                                       const float* __restrict__ g,
                                       const float* __restrict__ bb, int lane) {
    float4 v1 = *(const float4*)(in + lane * 4);
    float4 v2 = *(const float4*)(in + 128 + lane * 4);
    float s = v1.x + v1.y + v1.z + v1.w + v2.x + v2.y + v2.z + v2.w;
    float ss = v1.x * v1.x + v1.y * v1.y + v1.z * v1.z + v1.w * v1.w
             + v2.x * v2.x + v2.y * v2.y + v2.z * v2.z + v2.w * v2.w;
    wred2(s, ss);
    float m = s * (1.f / 256.f);
    float rs = rsqrtf(ss * (1.f / 256.f) - m * m + 1e-5f);
    int d = lane * 4;
    float4 ga = *(const float4*)(g + d), ba = *(const float4*)(bb + d);
    out[d + 0] = (v1.x - m) * rs * ga.x + ba.x;
    out[d + 1] = (v1.y - m) * rs * ga.y + ba.y;
    out[d + 2] = (v1.z - m) * rs * ga.z + ba.z;
    out[d + 3] = (v1.w - m) * rs * ga.w + ba.w;
    int d2 = d + 128;
    float4 gb = *(const float4*)(g + d2), bbv = *(const float4*)(bb + d2);
    out[d2 + 0] = (v2.x - m) * rs * gb.x + bbv.x;
    out[d2 + 1] = (v2.y - m) * rs * gb.y + bbv.y;
    out[d2 + 2] = (v2.z - m) * rs * gb.z + bbv.z;
    out[d2 + 3] = (v2.w - m) * rs * gb.w + bbv.w;
}

// ---------------- one-time kernels -------------------------------------------
__global__ void k_init_slots(const float* __restrict__ noise,
                             const float* __restrict__ mu,
                             const float* __restrict__ ls) {
    int i = blockIdx.x * 256 + threadIdx.x;
    int d = i & 255;
    g_slots[i] = mu[d] + expf(ls[d]) * noise[i];
}

__global__ void __launch_bounds__(256) k_rowstats(const float* __restrict__ emb) {
    int row = blockIdx.x * 8 + (threadIdx.x >> 5);
    int lane = threadIdx.x & 31;
    const float4* er = (const float4*)(emb + (size_t)row * 256);
    float4 v1 = er[lane];
    float4 v2 = er[lane + 32];
    float s = v1.x + v1.y + v1.z + v1.w + v2.x + v2.y + v2.z + v2.w;
    float ss = v1.x * v1.x + v1.y * v1.y + v1.z * v1.z + v1.w * v1.w
             + v2.x * v2.x + v2.y * v2.y + v2.z * v2.z + v2.w * v2.w;
    wred2(s, ss);
    if (lane == 0) {
        float m = s * (1.f / 256.f);
        float rs = rsqrtf(ss * (1.f / 256.f) - m * m + 1e-5f);
        g_mr[row] = make_float2(m * rs, rs);
    }
}

// wqk2[e][f] = sum_d Wq[d,e] * Wk[d,f]
__global__ void __launch_bounds__(256) k_wqk(const float* __restrict__ Wq,
                                             const float* __restrict__ Wk) {
    __shared__ float sq[32][33], sk[32][33];
    int be = blockIdx.x, bf = blockIdx.y, tid = threadIdx.x;
    int dd = tid >> 3, e4 = (tid & 7) * 4;
    int ff = tid & 31, eo = (tid >> 5) * 4;
    float acc[4] = {};
    for (int d0 = 0; d0 < 256; d0 += 32) {
        float4 q4 = *(const float4*)(Wq + (size_t)(d0 + dd) * 256 + be * 32 + e4);
        float4 k4 = *(const float4*)(Wk + (size_t)(d0 + dd) * 256 + bf * 32 + e4);
        sq[dd][e4 + 0] = q4.x; sq[dd][e4 + 1] = q4.y; sq[dd][e4 + 2] = q4.z; sq[dd][e4 + 3] = q4.w;
        sk[dd][e4 + 0] = k4.x; sk[dd][e4 + 1] = k4.y; sk[dd][e4 + 2] = k4.z; sk[dd][e4 + 3] = k4.w;
        __syncthreads();
#pragma unroll
        for (int d = 0; d < 32; d++) {
            float kv = sk[d][ff];
            acc[0] += sq[d][eo + 0] * kv;
            acc[1] += sq[d][eo + 1] * kv;
            acc[2] += sq[d][eo + 2] * kv;
            acc[3] += sq[d][eo + 3] * kv;
        }
        __syncthreads();
    }
#pragma unroll
    for (int i = 0; i < 4; i++)
        g_wqk2[(size_t)(be * 32 + eo + i) * 256 + bf * 32 + ff] = acc[i];
}

// W [J][K] row-major -> Wt [K][J]
__global__ void __launch_bounds__(256) k_transpose(const float* __restrict__ W,
                                                   float* __restrict__ Wt,
                                                   int J, int K) {
    __shared__ float t[32][33];
    int j0 = blockIdx.x * 32, k0 = blockIdx.y * 32;
    int x = threadIdx.x & 31, y = threadIdx.x >> 5;
#pragma unroll
    for (int yy = y; yy < 32; yy += 8)
        t[yy][x] = W[(size_t)(j0 + yy) * K + k0 + x];
    __syncthreads();
#pragma unroll
    for (int yy = y; yy < 32; yy += 8)
        Wt[(size_t)(k0 + yy) * J + j0 + x] = t[x][yy];
}

// q-prep for iteration 0
__global__ void __launch_bounds__(256) k_prep0(const float* __restrict__ lslg,
                                               const float* __restrict__ lslb,
                                               const float* __restrict__ ling,
                                               const float* __restrict__ linb) {
    __shared__ __align__(16) float h[8][256], sn[8][256], qb_s[8][256];
    int b = blockIdx.x, tid = threadIdx.x, warp = tid >> 5, lane = tid & 31;
#pragma unroll
    for (int i = 0; i < 8; i++) {
        int idx = i * 256 + tid; int r = idx >> 8, e = idx & 255;
        h[r][e] = g_slots[(b * 8 + r) * 256 + e];
    }
    __syncthreads();
    ln_row(&h[warp][0], &sn[warp][0], lslg, lslb, lane);
    __syncthreads();
    int j = tid;
    float acc[8] = {};
#pragma unroll 8
    for (int e = 0; e < 256; e++) {
        float w = g_wqk2[(size_t)e * 256 + j];   // coalesced across threads
#pragma unroll
        for (int r = 0; r < 8; r++) acc[r] += w * sn[r][e];
    }
    float gv = ling[j] * 0.0625f, bv = linb[j] * 0.0625f;
#pragma unroll
    for (int r = 0; r < 8; r++) {
        float qgv = acc[r] * gv;
        g_q[(b * 8 + r) * 256 + j] = qgv;
        h[r][j] = qgv;
        qb_s[r][j] = acc[r] * bv;
    }
    __syncthreads();
    float s1v = 0.f, s2v = 0.f;
#pragma unroll
    for (int i = 0; i < 8; i++) {
        s1v += h[warp][lane + 32 * i];
        s2v += qb_s[warp][lane + 32 * i];
    }
    wred2(s1v, s2v);
    if (lane == 0) { g_qs1[b * 8 + warp] = s1v; g_qb[b * 8 + warp] = s2v; }
}

// ---------------- streaming attention (raw emb + folded LN scalars) --------
__global__ void __launch_bounds__(256) k_attn(const float* __restrict__ emb,
                                              float* __restrict__ attn_out) {
    __shared__ __align__(16) float qg[8][260];
    __shared__ __align__(16) float xt[32][260];
    __shared__ float2 mrs[32];
    __shared__ float at4[32][8];
    __shared__ float atp[32][8];
    __shared__ float rs_s[8][33];
    __shared__ float s2_s[8][33];

    int b = blockIdx.y, nb = blockIdx.x, tid = threadIdx.x;
    int kk = tid & 7, nl = tid >> 3;

    {   // stage qg
        const float4* qsrc = (const float4*)(g_q + b * 8 * 256);
#pragma unroll
        for (int i = 0; i < 2; i++) {
            int p = tid + i * 256; int r = p >> 6, c4 = p & 63;
            *(float4*)&qg[r][c4 * 4] = qsrc[p];
        }
    }
    float qs1k = g_qs1[b * 8 + kk], qbk = g_qb[b * 8 + kk];

    const float* esrc = emb + ((size_t)b * Nn + nb * 256) * 256;
    const float2* msrc = g_mr + (size_t)b * Nn + nb * 256;

    float aggr[8] = {};
    float rsl = 0.f, s2l = 0.f;

    for (int t = 0; t < 8; t++) {
        // stage 32 raw rows + stats (plain loads; R12-proven structure)
        const float* src = esrc + (size_t)t * 32 * 256;
#pragma unroll
        for (int i = 0; i < 8; i++) {
            int p = tid + i * 256; int r = p >> 6, c4 = p & 63;
            *(float4*)&xt[r][c4 * 4] = *(const float4*)(src + r * 256 + c4 * 4);
        }
        if (tid < 32) mrs[tid] = msrc[t * 32 + tid];
        __syncthreads();

        // dots: thread (kk, nl)
        float2 mrv = mrs[nl];
        const float* qr = &qg[kk][0];
        const float* xr = &xt[nl][0];
        float d0 = 0.f, d1 = 0.f, d2 = 0.f, d3 = 0.f;
#pragma unroll
        for (int c = 0; c < 64; c += 4) {
            float4 q0 = *(const float4*)(qr + c * 4),      x0 = *(const float4*)(xr + c * 4);
            float4 q1 = *(const float4*)(qr + c * 4 + 4),  x1 = *(const float4*)(xr + c * 4 + 4);
            float4 q2 = *(const float4*)(qr + c * 4 + 8),  x2 = *(const float4*)(xr + c * 4 + 8);
            float4 q3 = *(const float4*)(qr + c * 4 + 12), x3 = *(const float4*)(xr + c * 4 + 12);
            d0 += q0.x * x0.x + q0.y * x0.y + q0.z * x0.z + q0.w * x0.w;
            d1 += q1.x * x1.x + q1.y * x1.y + q1.z * x1.z + q1.w * x1.w;
            d2 += q2.x * x2.x + q2.y * x2.y + q2.z * x2.z + q2.w * x2.w;
            d3 += q3.x * x3.x + q3.y * x3.y + q3.z * x3.z + q3.w * x3.w;
        }
        float dval = mrv.y * ((d0 + d1) + (d2 + d3)) - mrv.x * qs1k + qbk;

        // softmax over the 8 slots (lanes xor 1,2,4 share nl)
        float mx = dval;
        mx = fmaxf(mx, __shfl_xor_sync(0xffffffffu, mx, 1));
        mx = fmaxf(mx, __shfl_xor_sync(0xffffffffu, mx, 2));
        mx = fmaxf(mx, __shfl_xor_sync(0xffffffffu, mx, 4));
        float ev = expf(dval - mx);
        float sm = ev;
        sm += __shfl_xor_sync(0xffffffffu, sm, 1);
        sm += __shfl_xor_sync(0xffffffffu, sm, 2);
        sm += __shfl_xor_sync(0xffffffffu, sm, 4);
        float a = ev / sm + 1e-8f;
        rsl += a;
        s2l += a * mrv.x;
        at4[nl][kk] = a * mrv.y;
        if (attn_out) atp[nl][kk] = a;
        __syncthreads();

        if (attn_out) {
            int k2 = tid >> 5, n2 = tid & 31;
            attn_out[(size_t)(b * 8 + k2) * Nn + nb * 256 + t * 32 + n2] = atp[n2][k2];
        }

        // agg accumulation in raw-x space: thread owns column e = tid
        const float* xcol = &xt[0][0];
#pragma unroll 4
        for (int n = 0; n < 32; n++) {
            float xv = xcol[n * 260 + tid];
            float4 a0 = *(const float4*)&at4[n][0];
            float4 a1 = *(const float4*)&at4[n][4];
            aggr[0] += a0.x * xv; aggr[1] += a0.y * xv;
            aggr[2] += a0.z * xv; aggr[3] += a0.w * xv;
            aggr[4] += a1.x * xv; aggr[5] += a1.y * xv;
            aggr[6] += a1.z * xv; aggr[7] += a1.w * xv;
        }
        __syncthreads();
    }

    rs_s[kk][nl] = rsl;
    s2_s[kk][nl] = s2l;
    __syncthreads();
    if (tid < 8) {
        float s = 0.f, s2 = 0.f;
#pragma unroll
        for (int i = 0; i < 32; i++) { s += rs_s[tid][i]; s2 += s2_s[tid][i]; }
        g_rsp[(nb * Bz + b) * 8 + tid] = s;
        g_s2p[(nb * Bz + b) * 8 + tid] = s2;
    }
    size_t base = (size_t)(nb * Bz + b) * 8 * 256;
#pragma unroll
    for (int k = 0; k < 8; k++) g_aggp[base + k * 256 + tid] = aggr[k];
}

// ---------------- fused: reduce -> upd -> GRU -> LN -> MLP -> next q' ------
// grid (Bz, 2): each block handles 4 slot-rows. 512 threads: j = tid&255,
// hf = tid>>8 splits K into halves; partials combined through smem.
struct FusedSmem {
    float ag[4][256], h[4][256], us[4][256], snew[4][256], sn[4][256];
    float p0[2][4][256], p1[2][4][256], p2[2][4][256], p3[2][4][256];
    float s1[4], s2[4], rinv[4];
};

__global__ void __launch_bounds__(512) k_fused(
    const float* __restrict__ b_ih, const float* __restrict__ b_hh,
    const float* __restrict__ b1, const float* __restrict__ b2,
    const float* __restrict__ lffg, const float* __restrict__ lffb,
    const float* __restrict__ lslg, const float* __restrict__ lslb,
    const float* __restrict__ ling, const float* __restrict__ linb,
    float* __restrict__ out_slots, int do_prep) {
    extern __shared__ char smem_raw[];
    FusedSmem* S = (FusedSmem*)smem_raw;
    int b = blockIdx.x, r0 = blockIdx.y * 4, tid = threadIdx.x;
    int j = tid & 255, hf = tid >> 8, k0 = hf * 128;
    int warp = tid >> 5, lane = tid & 31;

    // ---- stage a: reduce partials, load slots ----
    if (tid < 4) {
        float s1 = 0.f, s2 = 0.f;
#pragma unroll
        for (int nb = 0; nb < NB; nb++) {
            s1 += g_rsp[(nb * Bz + b) * 8 + r0 + tid];
            s2 += g_s2p[(nb * Bz + b) * 8 + r0 + tid];
        }
        S->s1[tid] = s1; S->s2[tid] = s2; S->rinv[tid] = 1.f / s1;
    }
#pragma unroll
    for (int i = 0; i < 2; i++) {
        int idx = tid + i * 512; int r = idx >> 8, e = idx & 255;
        float a = 0.f;
#pragma unroll
        for (int nb = 0; nb < NB; nb++)
            a += g_aggp[((size_t)(nb * Bz + b) * 8 + r0 + r) * 256 + e];
        S->ag[r][e] = a;
        S->h[r][e] = g_slots[(b * 8 + r0 + r) * 256 + e];
    }
    __syncthreads();
#pragma unroll
    for (int i = 0; i < 2; i++) {
        int idx = tid + i * 512; int r = idx >> 8, e = idx & 255;
        S->ag[r][e] = ling[e] * (S->ag[r][e] - S->s2[r]) + linb[e] * S->s1[r];
    }
    __syncthreads();

    // ---- stage b: us = (agg @ Wv^T) / rowsum ----
    {
        float acc[4] = {};
#pragma unroll 8
        for (int k = 0; k < 128; k++) {
            float w = g_WvT[(size_t)(k0 + k) * 256 + j];
#pragma unroll
            for (int r = 0; r < 4; r++) acc[r] += w * S->ag[r][k0 + k];
        }
#pragma unroll
        for (int r = 0; r < 4; r++) S->p0[hf][r][j] = acc[r];
    }
    __syncthreads();
#pragma unroll
    for (int i = 0; i < 2; i++) {
        int idx = tid + i * 512; int r = idx >> 8, e = idx & 255;
        S->us[r][e] = (S->p0[0][r][e] + S->p0[1][r][e]) * S->rinv[r];
    }
    __syncthreads();

    // ---- stage c: all three GRU gates in one k-pass ----
    {
        float racc[4] = {}, zacc[4] = {}, nai[4] = {}, nah[4] = {};
#pragma unroll 4
        for (int k = 0; k < 128; k++) {
            const float* wi = g_WihT + (size_t)(k0 + k) * 768;
            const float* wh = g_WhhT + (size_t)(k0 + k) * 768;
            float wir = wi[j], wiz = wi[256 + j], win = wi[512 + j];
            float whr = wh[j], whz = wh[256 + j], whn = wh[512 + j];
#pragma unroll
            for (int r = 0; r < 4; r++) {
                float uv = S->us[r][k0 + k], hv = S->h[r][k0 + k];
                racc[r] += wir * uv + whr * hv;
                zacc[r] += wiz * uv + whz * hv;
                nai[r]  += win * uv;
                nah[r]  += whn * hv;
            }
        }
#pragma unroll
        for (int r = 0; r < 4; r++) {
            S->p0[hf][r][j] = racc[r]; S->p1[hf][r][j] = zacc[r];
            S->p2[hf][r][j] = nai[r];  S->p3[hf][r][j] = nah[r];
        }
    }
    __syncthreads();
#pragma unroll
    for (int i = 0; i < 2; i++) {
        int idx = tid + i * 512; int r = idx >> 8, e = idx & 255;
        float rr = 1.f / (1.f + expf(-(S->p0[0][r][e] + S->p0[1][r][e] + b_ih[e] + b_hh[e])));
        float zz = 1.f / (1.f + expf(-(S->p1[0][r][e] + S->p1[1][r][e] + b_ih[256 + e] + b_hh[256 + e])));
        float nn = tanhf(S->p2[0][r][e] + S->p2[1][r][e] + b_ih[512 + e]
                         + rr * (S->p3[0][r][e] + S->p3[1][r][e] + b_hh[512 + e]));
        S->snew[r][e] = (1.f - zz) * nn + zz * S->h[r][e];
    }
    __syncthreads();

    // ---- stage d: LN(snew) -> sn ----
    if (warp < 4) ln_row(&S->snew[warp][0], &S->sn[warp][0], lffg, lffb, lane);
    __syncthreads();

    // ---- stage e: MLP1 (leaky relu) -> ag ----
    {
        float acc[4] = {};
#pragma unroll 8
        for (int k = 0; k < 128; k++) {
            float w = g_W1T[(size_t)(k0 + k) * 256 + j];
#pragma unroll
            for (int r = 0; r < 4; r++) acc[r] += w * S->sn[r][k0 + k];
        }
#pragma unroll
        for (int r = 0; r < 4; r++) S->p0[hf][r][j] = acc[r];
    }
    __syncthreads();
#pragma unroll
    for (int i = 0; i < 2; i++) {
        int idx = tid + i * 512; int r = idx >> 8, e = idx & 255;
        float t = S->p0[0][r][e] + S->p0[1][r][e] + b1[e];
        S->ag[r][e] = (t > 0.f) ? t : 0.01f * t;
    }
    __syncthreads();

    // ---- stage f: MLP2 + residual -> slots ----
    {
        float acc[4] = {};
#pragma unroll 8
        for (int k = 0; k < 128; k++) {
            float w = g_W2T[(size_t)(k0 + k) * 256 + j];
#pragma unroll
            for (int r = 0; r < 4; r++) acc[r] += w * S->ag[r][k0 + k];
        }
#pragma unroll
        for (int r = 0; r < 4; r++) S->p0[hf][r][j] = acc[r];
    }
    __syncthreads();
#pragma unroll
    for (int i = 0; i < 2; i++) {
        int idx = tid + i * 512; int r = idx >> 8, e = idx & 255;
        float o = S->snew[r][e] + S->p0[0][r][e] + S->p0[1][r][e] + b2[e];
        g_slots[(b * 8 + r0 + r) * 256 + e] = o;
        if (out_slots) out_slots[(b * 8 + r0 + r) * 256 + e] = o;
        S->h[r][e] = o;
    }
    __syncthreads();

    // ---- stage g: prep next iteration's qg / qs1 / qb ----
    if (do_prep) {
        if (warp < 4) ln_row(&S->h[warp][0], &S->sn[warp][0], lslg, lslb, lane);
        __syncthreads();
        {
            float acc[4] = {};
#pragma unroll 8
            for (int k = 0; k < 128; k++) {
                float w = g_wqk2[(size_t)(k0 + k) * 256 + j];
#pragma unroll
                for (int r = 0; r < 4; r++) acc[r] += w * S->sn[r][k0 + k];
            }
#pragma unroll
            for (int r = 0; r < 4; r++) S->p0[hf][r][j] = acc[r];
        }
        __syncthreads();
#pragma unroll
        for (int i = 0; i < 2; i++) {
            int idx = tid + i * 512; int r = idx >> 8, e = idx & 255;
            float qp = S->p0[0][r][e] + S->p0[1][r][e];
            float qgv = 0.0625f * qp * ling[e];
            g_q[(b * 8 + r0 + r) * 256 + e] = qgv;
            S->us[r][e] = qgv;
            S->snew[r][e] = 0.0625f * qp * linb[e];
        }
        __syncthreads();
        if (warp < 4) {
            float s1v = 0.f, s2v = 0.f;
#pragma unroll
            for (int i = 0; i < 8; i++) {
                s1v += S->us[warp][lane + 32 * i];
                s2v += S->snew[warp][lane + 32 * i];
            }
            wred2(s1v, s2v);
            if (lane == 0) {
                g_qs1[b * 8 + r0 + warp] = s1v;
                g_qb[b * 8 + r0 + warp] = s2v;
            }
        }
    }
}

// ---------------- launch ------------------------------------------------------
extern "C" void kernel_launch(void* const* d_in, const int* in_sizes, int n_in,
                              void* d_out, int out_size) {
    const float* emb   = (const float*)d_in[0];
    const float* noise = (const float*)d_in[1];
    const float* mu    = (const float*)d_in[2];
    const float* ls    = (const float*)d_in[3];
    const float* Wq    = (const float*)d_in[4];
    const float* Wk    = (const float*)d_in[5];
    const float* Wv    = (const float*)d_in[6];
    const float* W_ih  = (const float*)d_in[7];
    const float* W_hh  = (const float*)d_in[8];
    const float* b_ih  = (const float*)d_in[9];
    const float* b_hh  = (const float*)d_in[10];
    const float* W1    = (const float*)d_in[11];
    const float* b1    = (const float*)d_in[12];
    const float* W2    = (const float*)d_in[13];
    const float* b2    = (const float*)d_in[14];
    const float* lin_g = (const float*)d_in[15];
    const float* lin_b = (const float*)d_in[16];
    const float* lsl_g = (const float*)d_in[17];
    const float* lsl_b = (const float*)d_in[18];
    const float* lff_g = (const float*)d_in[19];
    const float* lff_b = (const float*)d_in[20];

    float* out       = (float*)d_out;
    float* out_slots = out;                  // [B,K,D]
    float* out_attn  = out + Bz * Kk * Dd;   // [B,K,N]

    float* wvT = nullptr, *wihT = nullptr, *whhT = nullptr, *w1T = nullptr, *w2T = nullptr;
    cudaGetSymbolAddress((void**)&wvT,  g_WvT);
    cudaGetSymbolAddress((void**)&wihT, g_WihT);
    cudaGetSymbolAddress((void**)&whhT, g_WhhT);
    cudaGetSymbolAddress((void**)&w1T,  g_W1T);
    cudaGetSymbolAddress((void**)&w2T,  g_W2T);

    cudaFuncSetAttribute(k_fused, cudaFuncAttributeMaxDynamicSharedMemorySize,
                         (int)sizeof(FusedSmem));

    k_init_slots<<<(Bz * Kk * Dd) / 256, 256>>>(noise, mu, ls);
    k_rowstats<<<(Bz * Nn) / 8, 256>>>(emb);
    k_wqk<<<dim3(8, 8), 256>>>(Wq, Wk);
    k_transpose<<<dim3(8, 8),  256>>>(Wv,   wvT,  256, 256);
    k_transpose<<<dim3(24, 8), 256>>>(W_ih, wihT, 768, 256);
    k_transpose<<<dim3(24, 8), 256>>>(W_hh, whhT, 768, 256);
    k_transpose<<<dim3(8, 8),  256>>>(W1,   w1T,  256, 256);
    k_transpose<<<dim3(8, 8),  256>>>(W2,   w2T,  256, 256);
    k_prep0<<<Bz, 256>>>(lsl_g, lsl_b, lin_g, lin_b);

    for (int it = 0; it < 3; it++) {
        k_attn<<<dim3(NB, Bz), 256>>>(emb, (it == 2) ? out_attn : nullptr);
        k_fused<<<dim3(Bz, 2), 512, sizeof(FusedSmem)>>>(
            b_ih, b_hh, b1, b2, lff_g, lff_b, lsl_g, lsl_b, lin_g, lin_b,
            (it == 2) ? out_slots : nullptr, (it < 2) ? 1 : 0);
    }
}

// round 15
// speedup vs baseline: 2.3809x; 1.3053x over previous
#include <cuda_runtime.h>
#include <cstddef>
#include <cstdint>

#define Bz 32
#define Nn 4096
#define Dd 256
#define Kk 8
#define NB 16              // n-chunks per batch in k_attn (256 rows each)

// ---------------- scratch (device globals; no allocations) -----------------
__device__ float  g_slots[Bz * Kk * Dd];
__device__ float  g_q[Bz * Kk * Dd];            // qg = SCALE * q' * ln_in_g
__device__ float  g_qs1[Bz * Kk];               // sum_e qg
__device__ float  g_qb[Bz * Kk];                // SCALE * q' . ln_in_b
__device__ float  g_aggp[(size_t)NB * Bz * Kk * Dd];  // partial sum_n (a*rs)*x
__device__ float  g_rsp[NB * Bz * Kk];          // partial sum_n a
__device__ float  g_s2p[NB * Bz * Kk];          // partial sum_n a*m*rs
__device__ float2 g_mr[(size_t)Bz * Nn];        // per emb row: (m*rs, rs)
// pair-interleaved transposed weights: Wt2[kp][j] = (W[j][2kp], W[j][2kp+1])
__device__ float2 g_wqk2p[(Dd / 2) * Dd];       // [ep][f]
__device__ float2 g_WvT2[(Dd / 2) * Dd];
__device__ float2 g_WihT2[(Dd / 2) * 3 * Dd];
__device__ float2 g_WhhT2[(Dd / 2) * 3 * Dd];
__device__ float2 g_W1T2[(Dd / 2) * Dd];
__device__ float2 g_W2T2[(Dd / 2) * Dd];

// ---------------- helpers ----------------------------------------------------
__device__ __forceinline__ void ffma2(float2& d, float2 a, float2 b) {
    asm("fma.rn.f32x2 %0, %1, %2, %0;"
        : "+l"(reinterpret_cast<unsigned long long&>(d))
        : "l"(reinterpret_cast<unsigned long long&>(a)),
          "l"(reinterpret_cast<unsigned long long&>(b)));
}

__device__ __forceinline__ void wred2(float& a, float& b) {
#pragma unroll
    for (int o = 16; o > 0; o >>= 1) {
        a += __shfl_xor_sync(0xffffffffu, a, o);
        b += __shfl_xor_sync(0xffffffffu, b, o);
    }
}

// LN over one 256-row in smem, one warp per row
__device__ __forceinline__ void ln_row(const float* __restrict__ in,
                                       float* __restrict__ out,
                                       const float* __restrict__ g,
                                       const float* __restrict__ bb, int lane) {
    float4 v1 = *(const float4*)(in + lane * 4);
    float4 v2 = *(const float4*)(in + 128 + lane * 4);
    float s = v1.x + v1.y + v1.z + v1.w + v2.x + v2.y + v2.z + v2.w;
    float ss = v1.x * v1.x + v1.y * v1.y + v1.z * v1.z + v1.w * v1.w
             + v2.x * v2.x + v2.y * v2.y + v2.z * v2.z + v2.w * v2.w;
    wred2(s, ss);
    float m = s * (1.f / 256.f);
    float rs = rsqrtf(ss * (1.f / 256.f) - m * m + 1e-5f);
    int d = lane * 4;
    float4 ga = *(const float4*)(g + d), ba = *(const float4*)(bb + d);
    out[d + 0] = (v1.x - m) * rs * ga.x + ba.x;
    out[d + 1] = (v1.y - m) * rs * ga.y + ba.y;
    out[d + 2] = (v1.z - m) * rs * ga.z + ba.z;
    out[d + 3] = (v1.w - m) * rs * ga.w + ba.w;
    int d2 = d + 128;
    float4 gb = *(const float4*)(g + d2), bbv = *(const float4*)(bb + d2);
    out[d2 + 0] = (v2.x - m) * rs * gb.x + bbv.x;
    out[d2 + 1] = (v2.y - m) * rs * gb.y + bbv.y;
    out[d2 + 2] = (v2.z - m) * rs * gb.z + bbv.z;
    out[d2 + 3] = (v2.w - m) * rs * gb.w + bbv.w;
}

// ---------------- one-time kernels -------------------------------------------
__global__ void k_init_slots(const float* __restrict__ noise,
                             const float* __restrict__ mu,
                             const float* __restrict__ ls) {
    int i = blockIdx.x * 256 + threadIdx.x;
    int d = i & 255;
    g_slots[i] = mu[d] + expf(ls[d]) * noise[i];
}

__global__ void __launch_bounds__(256) k_rowstats(const float* __restrict__ emb) {
    int row = blockIdx.x * 8 + (threadIdx.x >> 5);
    int lane = threadIdx.x & 31;
    const float4* er = (const float4*)(emb + (size_t)row * 256);
    float4 v1 = er[lane];
    float4 v2 = er[lane + 32];
    float s = v1.x + v1.y + v1.z + v1.w + v2.x + v2.y + v2.z + v2.w;
    float ss = v1.x * v1.x + v1.y * v1.y + v1.z * v1.z + v1.w * v1.w
             + v2.x * v2.x + v2.y * v2.y + v2.z * v2.z + v2.w * v2.w;
    wred2(s, ss);
    if (lane == 0) {
        float m = s * (1.f / 256.f);
        float rs = rsqrtf(ss * (1.f / 256.f) - m * m + 1e-5f);
        g_mr[row] = make_float2(m * rs, rs);
    }
}

// wqk2p[e/2][f] pairs of: sum_d Wq[d,e] * Wk[d,f]
__global__ void __launch_bounds__(256) k_wqk(const float* __restrict__ Wq,
                                             const float* __restrict__ Wk) {
    __shared__ float sq[32][33], sk[32][33];
    int be = blockIdx.x, bf = blockIdx.y, tid = threadIdx.x;
    int dd = tid >> 3, e4 = (tid & 7) * 4;
    int ff = tid & 31, eo = (tid >> 5) * 4;
    float acc[4] = {};
    for (int d0 = 0; d0 < 256; d0 += 32) {
        float4 q4 = *(const float4*)(Wq + (size_t)(d0 + dd) * 256 + be * 32 + e4);
        float4 k4 = *(const float4*)(Wk + (size_t)(d0 + dd) * 256 + bf * 32 + e4);
        sq[dd][e4 + 0] = q4.x; sq[dd][e4 + 1] = q4.y; sq[dd][e4 + 2] = q4.z; sq[dd][e4 + 3] = q4.w;
        sk[dd][e4 + 0] = k4.x; sk[dd][e4 + 1] = k4.y; sk[dd][e4 + 2] = k4.z; sk[dd][e4 + 3] = k4.w;
        __syncthreads();
#pragma unroll
        for (int d = 0; d < 32; d++) {
            float kv = sk[d][ff];
            acc[0] += sq[d][eo + 0] * kv;
            acc[1] += sq[d][eo + 1] * kv;
            acc[2] += sq[d][eo + 2] * kv;
            acc[3] += sq[d][eo + 3] * kv;
        }
        __syncthreads();
    }
    int ep = be * 16 + eo / 2, f = bf * 32 + ff;
    g_wqk2p[(size_t)ep * 256 + f]       = make_float2(acc[0], acc[1]);
    g_wqk2p[(size_t)(ep + 1) * 256 + f] = make_float2(acc[2], acc[3]);
}

// W [J][K] row-major -> Wt2 [K/2][J] pair-interleaved
__global__ void __launch_bounds__(256) k_transpose2(const float* __restrict__ W,
                                                    float2* __restrict__ Wt2,
                                                    int J, int K) {
    __shared__ float t[32][33];
    int j0 = blockIdx.x * 32, k0 = blockIdx.y * 32;
    int x = threadIdx.x & 31, y = threadIdx.x >> 5;
#pragma unroll
    for (int yy = y; yy < 32; yy += 8)
        t[yy][x] = W[(size_t)(j0 + yy) * K + k0 + x];
    __syncthreads();
#pragma unroll
    for (int kp = y; kp < 16; kp += 8)
        Wt2[(size_t)(k0 / 2 + kp) * J + j0 + x] = make_float2(t[x][2 * kp], t[x][2 * kp + 1]);
}

// q-prep for iteration 0
__global__ void __launch_bounds__(256) k_prep0(const float* __restrict__ lslg,
                                               const float* __restrict__ lslb,
                                               const float* __restrict__ ling,
                                               const float* __restrict__ linb) {
    __shared__ __align__(16) float h[8][256], sn[8][256], qb_s[8][256];
    int b = blockIdx.x, tid = threadIdx.x, warp = tid >> 5, lane = tid & 31;
#pragma unroll
    for (int i = 0; i < 8; i++) {
        int idx = i * 256 + tid; int r = idx >> 8, e = idx & 255;
        h[r][e] = g_slots[(b * 8 + r) * 256 + e];
    }
    __syncthreads();
    ln_row(&h[warp][0], &sn[warp][0], lslg, lslb, lane);
    __syncthreads();
    int j = tid;
    float2 acc2[8] = {};
#pragma unroll 8
    for (int ep = 0; ep < 128; ep++) {
        float2 w2 = g_wqk2p[(size_t)ep * 256 + j];
#pragma unroll
        for (int r = 0; r < 8; r++)
            ffma2(acc2[r], w2, *(const float2*)&sn[r][2 * ep]);
    }
    float gv = ling[j] * 0.0625f, bv = linb[j] * 0.0625f;
#pragma unroll
    for (int r = 0; r < 8; r++) {
        float a = acc2[r].x + acc2[r].y;
        float qgv = a * gv;
        g_q[(b * 8 + r) * 256 + j] = qgv;
        h[r][j] = qgv;
        qb_s[r][j] = a * bv;
    }
    __syncthreads();
    float s1v = 0.f, s2v = 0.f;
#pragma unroll
    for (int i = 0; i < 8; i++) {
        s1v += h[warp][lane + 32 * i];
        s2v += qb_s[warp][lane + 32 * i];
    }
    wred2(s1v, s2v);
    if (lane == 0) { g_qs1[b * 8 + warp] = s1v; g_qb[b * 8 + warp] = s2v; }
}

// ---------------- streaming attention (64-row tiles, f32x2) -----------------
struct AttnSmem {
    float  qg[8][260];
    float  xt[64][260];
    float2 mrs[64];
    float  at4[64][8];
    float  atp[64][8];
    float  rs_s[8][33];
    float  s2_s[8][33];
};

__global__ void __launch_bounds__(256) k_attn(const float* __restrict__ emb,
                                              float* __restrict__ attn_out) {
    extern __shared__ char smraw[];
    AttnSmem* S = (AttnSmem*)smraw;
    int b = blockIdx.y, nb = blockIdx.x, tid = threadIdx.x;
    int kk = tid & 7, nlp = tid >> 3;

    {   // stage qg
        const float4* qsrc = (const float4*)(g_q + b * 8 * 256);
#pragma unroll
        for (int i = 0; i < 2; i++) {
            int p = tid + i * 256; int r = p >> 6, c4 = p & 63;
            *(float4*)&S->qg[r][c4 * 4] = qsrc[p];
        }
    }
    float qs1k = g_qs1[b * 8 + kk], qbk = g_qb[b * 8 + kk];

    const float* esrc = emb + ((size_t)b * Nn + nb * 256) * 256;
    const float2* msrc = g_mr + (size_t)b * Nn + nb * 256;

    float2 aggr[4] = {};            // packed (k0,k1)(k2,k3)(k4,k5)(k6,k7)
    float rsl = 0.f, s2l = 0.f;

    for (int t = 0; t < 4; t++) {
        // stage 64 raw rows + stats
        const float* src = esrc + (size_t)t * 64 * 256;
#pragma unroll
        for (int i = 0; i < 16; i++) {
            int p = tid + i * 256; int r = p >> 6, c4 = p & 63;
            *(float4*)&S->xt[r][c4 * 4] = *(const float4*)(src + r * 256 + c4 * 4);
        }
        if (tid < 64) S->mrs[tid] = msrc[t * 64 + tid];
        __syncthreads();

        // dots for rows nlp and nlp+32 (q loaded once for both)
        float2 mr0 = S->mrs[nlp], mr1 = S->mrs[nlp + 32];
        const float4* qr  = (const float4*)&S->qg[kk][0];
        const float4* xr0 = (const float4*)&S->xt[nlp][0];
        const float4* xr1 = (const float4*)&S->xt[nlp + 32][0];
        float2 a0 = {0.f, 0.f}, a1 = {0.f, 0.f}, c0 = {0.f, 0.f}, c1 = {0.f, 0.f};
#pragma unroll 16
        for (int c = 0; c < 64; c++) {
            float4 q4 = qr[c], xa = xr0[c], xb = xr1[c];
            ffma2(a0, make_float2(q4.x, q4.y), make_float2(xa.x, xa.y));
            ffma2(a1, make_float2(q4.z, q4.w), make_float2(xa.z, xa.w));
            ffma2(c0, make_float2(q4.x, q4.y), make_float2(xb.x, xb.y));
            ffma2(c1, make_float2(q4.z, q4.w), make_float2(xb.z, xb.w));
        }
        float dv0 = mr0.y * ((a0.x + a0.y) + (a1.x + a1.y)) - mr0.x * qs1k + qbk;
        float dv1 = mr1.y * ((c0.x + c0.y) + (c1.x + c1.y)) - mr1.x * qs1k + qbk;

        // softmax over the 8 slots (lanes xor 1,2,4 share the row)
        float mx0 = dv0, mx1 = dv1;
#pragma unroll
        for (int o = 1; o <= 4; o <<= 1) {
            mx0 = fmaxf(mx0, __shfl_xor_sync(0xffffffffu, mx0, o));
            mx1 = fmaxf(mx1, __shfl_xor_sync(0xffffffffu, mx1, o));
        }
        float e0 = expf(dv0 - mx0), e1 = expf(dv1 - mx1);
        float sm0 = e0, sm1 = e1;
#pragma unroll
        for (int o = 1; o <= 4; o <<= 1) {
            sm0 += __shfl_xor_sync(0xffffffffu, sm0, o);
            sm1 += __shfl_xor_sync(0xffffffffu, sm1, o);
        }
        float av0 = e0 / sm0 + 1e-8f, av1 = e1 / sm1 + 1e-8f;
        rsl += av0 + av1;
        s2l += av0 * mr0.x + av1 * mr1.x;
        S->at4[nlp][kk]      = av0 * mr0.y;
        S->at4[nlp + 32][kk] = av1 * mr1.y;
        if (attn_out) { S->atp[nlp][kk] = av0; S->atp[nlp + 32][kk] = av1; }
        __syncthreads();

        if (attn_out) {
            int k2 = tid >> 5, n2 = tid & 31;
            size_t o = (size_t)(b * 8 + k2) * Nn + nb * 256 + t * 64;
            attn_out[o + n2]      = S->atp[n2][k2];
            attn_out[o + 32 + n2] = S->atp[n2 + 32][k2];
        }

        // agg: thread owns column e = tid; at4 rows broadcast
#pragma unroll 4
        for (int n = 0; n < 64; n++) {
            float xv = S->xt[n][tid];
            float2 xv2 = make_float2(xv, xv);
            const float4* ap = (const float4*)&S->at4[n][0];
            float4 aa = ap[0], ab = ap[1];
            ffma2(aggr[0], make_float2(aa.x, aa.y), xv2);
            ffma2(aggr[1], make_float2(aa.z, aa.w), xv2);
            ffma2(aggr[2], make_float2(ab.x, ab.y), xv2);
            ffma2(aggr[3], make_float2(ab.z, ab.w), xv2);
        }
        __syncthreads();
    }

    S->rs_s[kk][nlp] = rsl;
    S->s2_s[kk][nlp] = s2l;
    __syncthreads();
    if (tid < 8) {
        float s = 0.f, s2 = 0.f;
#pragma unroll
        for (int i = 0; i < 32; i++) { s += S->rs_s[tid][i]; s2 += S->s2_s[tid][i]; }
        g_rsp[(nb * Bz + b) * 8 + tid] = s;
        g_s2p[(nb * Bz + b) * 8 + tid] = s2;
    }
    size_t base = (size_t)(nb * Bz + b) * 8 * 256;
#pragma unroll
    for (int p = 0; p < 4; p++) {
        g_aggp[base + (2 * p)     * 256 + tid] = aggr[p].x;
        g_aggp[base + (2 * p + 1) * 256 + tid] = aggr[p].y;
    }
}

// ---------------- fused: reduce -> upd -> GRU -> LN -> MLP -> next q' ------
struct FusedSmem {
    float ag[4][256], h[4][256], us[4][256], snew[4][256], sn[4][256];
    float p0[2][4][256], p1[2][4][256], p2[2][4][256], p3[2][4][256];
    float s1[4], s2[4], rinv[4];
};

__global__ void __launch_bounds__(512) k_fused(
    const float* __restrict__ b_ih, const float* __restrict__ b_hh,
    const float* __restrict__ b1, const float* __restrict__ b2,
    const float* __restrict__ lffg, const float* __restrict__ lffb,
    const float* __restrict__ lslg, const float* __restrict__ lslb,
    const float* __restrict__ ling, const float* __restrict__ linb,
    float* __restrict__ out_slots, int do_prep) {
    extern __shared__ char smem_raw[];
    FusedSmem* S = (FusedSmem*)smem_raw;
    int b = blockIdx.x, r0 = blockIdx.y * 4, tid = threadIdx.x;
    int j = tid & 255, hf = tid >> 8, kq0 = hf * 64;   // pair-index base
    int warp = tid >> 5, lane = tid & 31;

    // ---- stage a: reduce partials, load slots ----
    if (tid < 4) {
        float s1 = 0.f, s2 = 0.f;
#pragma unroll
        for (int nb = 0; nb < NB; nb++) {
            s1 += g_rsp[(nb * Bz + b) * 8 + r0 + tid];
            s2 += g_s2p[(nb * Bz + b) * 8 + r0 + tid];
        }
        S->s1[tid] = s1; S->s2[tid] = s2; S->rinv[tid] = 1.f / s1;
    }
#pragma unroll
    for (int i = 0; i < 2; i++) {
        int idx = tid + i * 512; int r = idx >> 8, e = idx & 255;
        float a = 0.f;
#pragma unroll
        for (int nb = 0; nb < NB; nb++)
            a += g_aggp[((size_t)(nb * Bz + b) * 8 + r0 + r) * 256 + e];
        S->ag[r][e] = a;
        S->h[r][e] = g_slots[(b * 8 + r0 + r) * 256 + e];
    }
    __syncthreads();
#pragma unroll
    for (int i = 0; i < 2; i++) {
        int idx = tid + i * 512; int r = idx >> 8, e = idx & 255;
        S->ag[r][e] = ling[e] * (S->ag[r][e] - S->s2[r]) + linb[e] * S->s1[r];
    }
    __syncthreads();

    // ---- stage b: us = (agg @ Wv^T) / rowsum ----
    {
        float2 acc2[4] = {};
#pragma unroll 8
        for (int kp = 0; kp < 64; kp++) {
            float2 w2 = g_WvT2[(size_t)(kq0 + kp) * 256 + j];
#pragma unroll
            for (int r = 0; r < 4; r++)
                ffma2(acc2[r], w2, *(const float2*)&S->ag[r][2 * (kq0 + kp)]);
        }
#pragma unroll
        for (int r = 0; r < 4; r++) S->p0[hf][r][j] = acc2[r].x + acc2[r].y;
    }
    __syncthreads();
#pragma unroll
    for (int i = 0; i < 2; i++) {
        int idx = tid + i * 512; int r = idx >> 8, e = idx & 255;
        S->us[r][e] = (S->p0[0][r][e] + S->p0[1][r][e]) * S->rinv[r];
    }
    __syncthreads();

    // ---- stage c: all three GRU gates in one k-pass ----
    {
        float2 racc[4] = {}, zacc[4] = {}, nai[4] = {}, nah[4] = {};
#pragma unroll 4
        for (int kp = 0; kp < 64; kp++) {
            const float2* wi = g_WihT2 + (size_t)(kq0 + kp) * 768;
            const float2* wh = g_WhhT2 + (size_t)(kq0 + kp) * 768;
            float2 wir = wi[j], wiz = wi[256 + j], win = wi[512 + j];
            float2 whr = wh[j], whz = wh[256 + j], whn = wh[512 + j];
#pragma unroll
            for (int r = 0; r < 4; r++) {
                float2 u2 = *(const float2*)&S->us[r][2 * (kq0 + kp)];
                float2 h2 = *(const float2*)&S->h[r][2 * (kq0 + kp)];
                ffma2(racc[r], wir, u2); ffma2(racc[r], whr, h2);
                ffma2(zacc[r], wiz, u2); ffma2(zacc[r], whz, h2);
                ffma2(nai[r],  win, u2); ffma2(nah[r],  whn, h2);
            }
        }
#pragma unroll
        for (int r = 0; r < 4; r++) {
            S->p0[hf][r][j] = racc[r].x + racc[r].y;
            S->p1[hf][r][j] = zacc[r].x + zacc[r].y;
            S->p2[hf][r][j] = nai[r].x + nai[r].y;
            S->p3[hf][r][j] = nah[r].x + nah[r].y;
        }
    }
    __syncthreads();
#pragma unroll
    for (int i = 0; i < 2; i++) {
        int idx = tid + i * 512; int r = idx >> 8, e = idx & 255;
        float rr = 1.f / (1.f + expf(-(S->p0[0][r][e] + S->p0[1][r][e] + b_ih[e] + b_hh[e])));
        float zz = 1.f / (1.f + expf(-(S->p1[0][r][e] + S->p1[1][r][e] + b_ih[256 + e] + b_hh[256 + e])));
        float nn = tanhf(S->p2[0][r][e] + S->p2[1][r][e] + b_ih[512 + e]
                         + rr * (S->p3[0][r][e] + S->p3[1][r][e] + b_hh[512 + e]));
        S->snew[r][e] = (1.f - zz) * nn + zz * S->h[r][e];
    }
    __syncthreads();

    // ---- stage d: LN(snew) -> sn ----
    if (warp < 4) ln_row(&S->snew[warp][0], &S->sn[warp][0], lffg, lffb, lane);
    __syncthreads();

    // ---- stage e: MLP1 (leaky relu) ----
    {
        float2 acc2[4] = {};
#pragma unroll 8
        for (int kp = 0; kp < 64; kp++) {
            float2 w2 = g_W1T2[(size_t)(kq0 + kp) * 256 + j];
#pragma unroll
            for (int r = 0; r < 4; r++)
                ffma2(acc2[r], w2, *(const float2*)&S->sn[r][2 * (kq0 + kp)]);
        }
#pragma unroll
        for (int r = 0; r < 4; r++) S->p0[hf][r][j] = acc2[r].x + acc2[r].y;
    }
    __syncthreads();
#pragma unroll
    for (int i = 0; i < 2; i++) {
        int idx = tid + i * 512; int r = idx >> 8, e = idx & 255;
        float t = S->p0[0][r][e] + S->p0[1][r][e] + b1[e];
        S->ag[r][e] = (t > 0.f) ? t : 0.01f * t;
    }
    __syncthreads();

    // ---- stage f: MLP2 + residual -> slots ----
    {
        float2 acc2[4] = {};
#pragma unroll 8
        for (int kp = 0; kp < 64; kp++) {
            float2 w2 = g_W2T2[(size_t)(kq0 + kp) * 256 + j];
#pragma unroll
            for (int r = 0; r < 4; r++)
                ffma2(acc2[r], w2, *(const float2*)&S->ag[r][2 * (kq0 + kp)]);
        }
#pragma unroll
        for (int r = 0; r < 4; r++) S->p0[hf][r][j] = acc2[r].x + acc2[r].y;
    }
    __syncthreads();
#pragma unroll
    for (int i = 0; i < 2; i++) {
        int idx = tid + i * 512; int r = idx >> 8, e = idx & 255;
        float o = S->snew[r][e] + S->p0[0][r][e] + S->p0[1][r][e] + b2[e];
        g_slots[(b * 8 + r0 + r) * 256 + e] = o;
        if (out_slots) out_slots[(b * 8 + r0 + r) * 256 + e] = o;
        S->h[r][e] = o;
    }
    __syncthreads();

    // ---- stage g: prep next iteration's qg / qs1 / qb ----
    if (do_prep) {
        if (warp < 4) ln_row(&S->h[warp][0], &S->sn[warp][0], lslg, lslb, lane);
        __syncthreads();
        {
            float2 acc2[4] = {};
#pragma unroll 8
            for (int kp = 0; kp < 64; kp++) {
                float2 w2 = g_wqk2p[(size_t)(kq0 + kp) * 256 + j];
#pragma unroll
                for (int r = 0; r < 4; r++)
                    ffma2(acc2[r], w2, *(const float2*)&S->sn[r][2 * (kq0 + kp)]);
            }
#pragma unroll
            for (int r = 0; r < 4; r++) S->p0[hf][r][j] = acc2[r].x + acc2[r].y;
        }
        __syncthreads();
#pragma unroll
        for (int i = 0; i < 2; i++) {
            int idx = tid + i * 512; int r = idx >> 8, e = idx & 255;
            float qp = S->p0[0][r][e] + S->p0[1][r][e];
            float qgv = 0.0625f * qp * ling[e];
            g_q[(b * 8 + r0 + r) * 256 + e] = qgv;
            S->us[r][e] = qgv;
            S->snew[r][e] = 0.0625f * qp * linb[e];
        }
        __syncthreads();
        if (warp < 4) {
            float s1v = 0.f, s2v = 0.f;
#pragma unroll
            for (int i = 0; i < 8; i++) {
                s1v += S->us[warp][lane + 32 * i];
                s2v += S->snew[warp][lane + 32 * i];
            }
            wred2(s1v, s2v);
            if (lane == 0) {
                g_qs1[b * 8 + r0 + warp] = s1v;
                g_qb[b * 8 + r0 + warp] = s2v;
            }
        }
    }
}

// ---------------- launch ------------------------------------------------------
extern "C" void kernel_launch(void* const* d_in, const int* in_sizes, int n_in,
                              void* d_out, int out_size) {
    const float* emb   = (const float*)d_in[0];
    const float* noise = (const float*)d_in[1];
    const float* mu    = (const float*)d_in[2];
    const float* ls    = (const float*)d_in[3];
    const float* Wq    = (const float*)d_in[4];
    const float* Wk    = (const float*)d_in[5];
    const float* Wv    = (const float*)d_in[6];
    const float* W_ih  = (const float*)d_in[7];
    const float* W_hh  = (const float*)d_in[8];
    const float* b_ih  = (const float*)d_in[9];
    const float* b_hh  = (const float*)d_in[10];
    const float* W1    = (const float*)d_in[11];
    const float* b1    = (const float*)d_in[12];
    const float* W2    = (const float*)d_in[13];
    const float* b2    = (const float*)d_in[14];
    const float* lin_g = (const float*)d_in[15];
    const float* lin_b = (const float*)d_in[16];
    const float* lsl_g = (const float*)d_in[17];
    const float* lsl_b = (const float*)d_in[18];
    const float* lff_g = (const float*)d_in[19];
    const float* lff_b = (const float*)d_in[20];

    float* out       = (float*)d_out;
    float* out_slots = out;                  // [B,K,D]
    float* out_attn  = out + Bz * Kk * Dd;   // [B,K,N]

    float2 *wvT = nullptr, *wihT = nullptr, *whhT = nullptr, *w1T = nullptr, *w2T = nullptr;
    cudaGetSymbolAddress((void**)&wvT,  g_WvT2);
    cudaGetSymbolAddress((void**)&wihT, g_WihT2);
    cudaGetSymbolAddress((void**)&whhT, g_WhhT2);
    cudaGetSymbolAddress((void**)&w1T,  g_W1T2);
    cudaGetSymbolAddress((void**)&w2T,  g_W2T2);

    cudaFuncSetAttribute(k_attn, cudaFuncAttributeMaxDynamicSharedMemorySize,
                         (int)sizeof(AttnSmem));
    cudaFuncSetAttribute(k_fused, cudaFuncAttributeMaxDynamicSharedMemorySize,
                         (int)sizeof(FusedSmem));

    k_init_slots<<<(Bz * Kk * Dd) / 256, 256>>>(noise, mu, ls);
    k_rowstats<<<(Bz * Nn) / 8, 256>>>(emb);
    k_wqk<<<dim3(8, 8), 256>>>(Wq, Wk);
    k_transpose2<<<dim3(8, 8),  256>>>(Wv,   wvT,  256, 256);
    k_transpose2<<<dim3(24, 8), 256>>>(W_ih, wihT, 768, 256);
    k_transpose2<<<dim3(24, 8), 256>>>(W_hh, whhT, 768, 256);
    k_transpose2<<<dim3(8, 8),  256>>>(W1,   w1T,  256, 256);
    k_transpose2<<<dim3(8, 8),  256>>>(W2,   w2T,  256, 256);
    k_prep0<<<Bz, 256>>>(lsl_g, lsl_b, lin_g, lin_b);

    for (int it = 0; it < 3; it++) {
        k_attn<<<dim3(NB, Bz), 256, sizeof(AttnSmem)>>>(
            emb, (it == 2) ? out_attn : nullptr);
        k_fused<<<dim3(Bz, 2), 512, sizeof(FusedSmem)>>>(
            b_ih, b_hh, b1, b2, lff_g, lff_b, lsl_g, lsl_b, lin_g, lin_b,
            (it == 2) ? out_slots : nullptr, (it < 2) ? 1 : 0);
    }
}

// round 16
// speedup vs baseline: 2.4510x; 1.0295x over previous
#include <cuda_runtime.h>
#include <cstddef>
#include <cstdint>

#define Bz 32
#define Nn 4096
#define Dd 256
#define Kk 8
#define NB 16              // n-chunks per batch in k_attn (256 rows each)

// ---------------- scratch (device globals; no allocations) -----------------
__device__ float  g_slots[Bz * Kk * Dd];
__device__ float  g_q[Bz * Kk * Dd];            // qg = SCALE * q' * ln_in_g
__device__ float  g_qs1[Bz * Kk];               // sum_e qg
__device__ float  g_qb[Bz * Kk];                // SCALE * q' . ln_in_b
__device__ float  g_aggp[(size_t)NB * Bz * Kk * Dd];  // partial sum_n (a*rs)*x
__device__ float  g_rsp[NB * Bz * Kk];          // partial sum_n a
__device__ float  g_s2p[NB * Bz * Kk];          // partial sum_n a*m*rs
__device__ float2 g_mr[(size_t)Bz * Nn];        // per emb row: (m*rs, rs)
// pair-interleaved transposed weights: Wt2[kp][j] = (W[j][2kp], W[j][2kp+1])
__device__ float2 g_wqk2p[(Dd / 2) * Dd];       // [ep][f]
__device__ float2 g_WvT2[(Dd / 2) * Dd];
__device__ float2 g_WihT2[(Dd / 2) * 3 * Dd];
__device__ float2 g_WhhT2[(Dd / 2) * 3 * Dd];
__device__ float2 g_W1T2[(Dd / 2) * Dd];
__device__ float2 g_W2T2[(Dd / 2) * Dd];

// ---------------- helpers ----------------------------------------------------
__device__ __forceinline__ void ffma2(float2& d, float2 a, float2 b) {
    asm("fma.rn.f32x2 %0, %1, %2, %0;"
        : "+l"(reinterpret_cast<unsigned long long&>(d))
        : "l"(reinterpret_cast<unsigned long long&>(a)),
          "l"(reinterpret_cast<unsigned long long&>(b)));
}

__device__ __forceinline__ void wred2(float& a, float& b) {
#pragma unroll
    for (int o = 16; o > 0; o >>= 1) {
        a += __shfl_xor_sync(0xffffffffu, a, o);
        b += __shfl_xor_sync(0xffffffffu, b, o);
    }
}

// LN over one 256-row in smem, one warp per row
__device__ __forceinline__ void ln_row(const float* __restrict__ in,
                                       float* __restrict__ out,
                                       const float* __restrict__ g,
                                       const float* __restrict__ bb, int lane) {
    float4 v1 = *(const float4*)(in + lane * 4);
    float4 v2 = *(const float4*)(in + 128 + lane * 4);
    float s = v1.x + v1.y + v1.z + v1.w + v2.x + v2.y + v2.z + v2.w;
    float ss = v1.x * v1.x + v1.y * v1.y + v1.z * v1.z + v1.w * v1.w
             + v2.x * v2.x + v2.y * v2.y + v2.z * v2.z + v2.w * v2.w;
    wred2(s, ss);
    float m = s * (1.f / 256.f);
    float rs = rsqrtf(ss * (1.f / 256.f) - m * m + 1e-5f);
    int d = lane * 4;
    float4 ga = *(const float4*)(g + d), ba = *(const float4*)(bb + d);
    out[d + 0] = (v1.x - m) * rs * ga.x + ba.x;
    out[d + 1] = (v1.y - m) * rs * ga.y + ba.y;
    out[d + 2] = (v1.z - m) * rs * ga.z + ba.z;
    out[d + 3] = (v1.w - m) * rs * ga.w + ba.w;
    int d2 = d + 128;
    float4 gb = *(const float4*)(g + d2), bbv = *(const float4*)(bb + d2);
    out[d2 + 0] = (v2.x - m) * rs * gb.x + bbv.x;
    out[d2 + 1] = (v2.y - m) * rs * gb.y + bbv.y;
    out[d2 + 2] = (v2.z - m) * rs * gb.z + bbv.z;
    out[d2 + 3] = (v2.w - m) * rs * gb.w + bbv.w;
}

// ---------------- merged setup: rowstats + slot init + 5 transposes ---------
#define RS_BLOCKS (Bz * Nn / 8)      // 16384
#define INIT_BLOCKS (Bz * Kk)        // 32 blocks of 256 = 65536 elems
__global__ void __launch_bounds__(256) k_setup(
    const float* __restrict__ emb,
    const float* __restrict__ noise, const float* __restrict__ mu,
    const float* __restrict__ ls,
    const float* __restrict__ Wv, const float* __restrict__ W_ih,
    const float* __restrict__ W_hh, const float* __restrict__ W1,
    const float* __restrict__ W2) {
    __shared__ float t[32][33];
    int blk = blockIdx.x, tid = threadIdx.x;
    if (blk < RS_BLOCKS) {
        int row = blk * 8 + (tid >> 5);
        int lane = tid & 31;
        const float4* er = (const float4*)(emb + (size_t)row * 256);
        float4 v1 = er[lane];
        float4 v2 = er[lane + 32];
        float s = v1.x + v1.y + v1.z + v1.w + v2.x + v2.y + v2.z + v2.w;
        float ss = v1.x * v1.x + v1.y * v1.y + v1.z * v1.z + v1.w * v1.w
                 + v2.x * v2.x + v2.y * v2.y + v2.z * v2.z + v2.w * v2.w;
        wred2(s, ss);
        if (lane == 0) {
            float m = s * (1.f / 256.f);
            float rs = rsqrtf(ss * (1.f / 256.f) - m * m + 1e-5f);
            g_mr[row] = make_float2(m * rs, rs);
        }
        return;
    }
    if (blk < RS_BLOCKS + INIT_BLOCKS) {
        int i = (blk - RS_BLOCKS) * 256 + tid;
        int d = i & 255;
        g_slots[i] = mu[d] + expf(ls[d]) * noise[i];
        return;
    }
    // transposes: all K = 256
    int w = blk - (RS_BLOCKS + INIT_BLOCKS);
    const float* W; float2* Wt2; int J, lw;
    if (w < 64)       { W = Wv;   Wt2 = g_WvT2;  J = 256; lw = w; }
    else if (w < 256) { W = W_ih; Wt2 = g_WihT2; J = 768; lw = w - 64; }
    else if (w < 448) { W = W_hh; Wt2 = g_WhhT2; J = 768; lw = w - 256; }
    else if (w < 512) { W = W1;   Wt2 = g_W1T2;  J = 256; lw = w - 448; }
    else              { W = W2;   Wt2 = g_W2T2;  J = 256; lw = w - 512; }
    int j0 = (lw >> 3) * 32, k0 = (lw & 7) * 32;
    int x = tid & 31, y = tid >> 5;
#pragma unroll
    for (int yy = y; yy < 32; yy += 8)
        t[yy][x] = W[(size_t)(j0 + yy) * 256 + k0 + x];
    __syncthreads();
#pragma unroll
    for (int kp = y; kp < 16; kp += 8)
        Wt2[(size_t)(k0 / 2 + kp) * J + j0 + x] = make_float2(t[x][2 * kp], t[x][2 * kp + 1]);
}

// wqk2p[e/2][f] pairs of: sum_d Wq[d,e] * Wk[d,f]
__global__ void __launch_bounds__(256) k_wqk(const float* __restrict__ Wq,
                                             const float* __restrict__ Wk) {
    __shared__ float sq[32][33], sk[32][33];
    int be = blockIdx.x, bf = blockIdx.y, tid = threadIdx.x;
    int dd = tid >> 3, e4 = (tid & 7) * 4;
    int ff = tid & 31, eo = (tid >> 5) * 4;
    float acc[4] = {};
    for (int d0 = 0; d0 < 256; d0 += 32) {
        float4 q4 = *(const float4*)(Wq + (size_t)(d0 + dd) * 256 + be * 32 + e4);
        float4 k4 = *(const float4*)(Wk + (size_t)(d0 + dd) * 256 + bf * 32 + e4);
        sq[dd][e4 + 0] = q4.x; sq[dd][e4 + 1] = q4.y; sq[dd][e4 + 2] = q4.z; sq[dd][e4 + 3] = q4.w;
        sk[dd][e4 + 0] = k4.x; sk[dd][e4 + 1] = k4.y; sk[dd][e4 + 2] = k4.z; sk[dd][e4 + 3] = k4.w;
        __syncthreads();
#pragma unroll
        for (int d = 0; d < 32; d++) {
            float kv = sk[d][ff];
            acc[0] += sq[d][eo + 0] * kv;
            acc[1] += sq[d][eo + 1] * kv;
            acc[2] += sq[d][eo + 2] * kv;
            acc[3] += sq[d][eo + 3] * kv;
        }
        __syncthreads();
    }
    int ep = be * 16 + eo / 2, f = bf * 32 + ff;
    g_wqk2p[(size_t)ep * 256 + f]       = make_float2(acc[0], acc[1]);
    g_wqk2p[(size_t)(ep + 1) * 256 + f] = make_float2(acc[2], acc[3]);
}

// q-prep for iteration 0
__global__ void __launch_bounds__(256) k_prep0(const float* __restrict__ lslg,
                                               const float* __restrict__ lslb,
                                               const float* __restrict__ ling,
                                               const float* __restrict__ linb) {
    __shared__ __align__(16) float h[8][256], sn[8][256], qb_s[8][256];
    int b = blockIdx.x, tid = threadIdx.x, warp = tid >> 5, lane = tid & 31;
#pragma unroll
    for (int i = 0; i < 8; i++) {
        int idx = i * 256 + tid; int r = idx >> 8, e = idx & 255;
        h[r][e] = g_slots[(b * 8 + r) * 256 + e];
    }
    __syncthreads();
    ln_row(&h[warp][0], &sn[warp][0], lslg, lslb, lane);
    __syncthreads();
    int j = tid;
    float2 acc2[8] = {};
#pragma unroll 8
    for (int ep = 0; ep < 128; ep++) {
        float2 w2 = g_wqk2p[(size_t)ep * 256 + j];
#pragma unroll
        for (int r = 0; r < 8; r++)
            ffma2(acc2[r], w2, *(const float2*)&sn[r][2 * ep]);
    }
    float gv = ling[j] * 0.0625f, bv = linb[j] * 0.0625f;
#pragma unroll
    for (int r = 0; r < 8; r++) {
        float a = acc2[r].x + acc2[r].y;
        float qgv = a * gv;
        g_q[(b * 8 + r) * 256 + j] = qgv;
        h[r][j] = qgv;
        qb_s[r][j] = a * bv;
    }
    __syncthreads();
    float s1v = 0.f, s2v = 0.f;
#pragma unroll
    for (int i = 0; i < 8; i++) {
        s1v += h[warp][lane + 32 * i];
        s2v += qb_s[warp][lane + 32 * i];
    }
    wred2(s1v, s2v);
    if (lane == 0) { g_qs1[b * 8 + warp] = s1v; g_qb[b * 8 + warp] = s2v; }
}

// ---------------- streaming attention (64-row tiles, 2x2 micro-tile) --------
struct AttnSmem {
    float2 qp[4][258];      // slot-pair-interleaved q: qp[p][e] = (qg[2p][e], qg[2p+1][e])
    float  xt[64][260];
    float2 mrs[64];
    float  at4[64][8];      // a * rs (for agg); attn recovered as at4/rs
    float  rs_s[8][33];
    float  s2_s[8][33];
};

__global__ void __launch_bounds__(256) k_attn(const float* __restrict__ emb,
                                              float* __restrict__ attn_out) {
    extern __shared__ char smraw[];
    AttnSmem* S = (AttnSmem*)smraw;
    int b = blockIdx.y, nb = blockIdx.x, tid = threadIdx.x;

    {   // build slot-pair-interleaved q
        int e = tid;
        const float* qsrc = g_q + b * 8 * 256;
#pragma unroll
        for (int p = 0; p < 4; p++)
            S->qp[p][e] = make_float2(qsrc[(2 * p) * 256 + e], qsrc[(2 * p + 1) * 256 + e]);
    }

    // dots thread mapping: p = tid&3 (slot pair), rp = tid>>2 (0..31) for tid<128
    int p = tid & 3, rp = tid >> 2;
    float2 qs1p = make_float2(g_qs1[b * 8 + 2 * p], g_qs1[b * 8 + 2 * p + 1]);
    float2 qbp  = make_float2(g_qb[b * 8 + 2 * p],  g_qb[b * 8 + 2 * p + 1]);

    const float* esrc = emb + ((size_t)b * Nn + nb * 256) * 256;
    const float2* msrc = g_mr + (size_t)b * Nn + nb * 256;

    float2 aggr[4] = {};            // packed (k0,k1)(k2,k3)(k4,k5)(k6,k7)
    float rs0 = 0.f, rs1 = 0.f, s20 = 0.f, s21 = 0.f;

    for (int t = 0; t < 4; t++) {
        // stage 64 raw rows + stats (all 256 threads)
        const float* src = esrc + (size_t)t * 64 * 256;
#pragma unroll
        for (int i = 0; i < 16; i++) {
            int pp = tid + i * 256; int r = pp >> 6, c4 = pp & 63;
            *(float4*)&S->xt[r][c4 * 4] = *(const float4*)(src + r * 256 + c4 * 4);
        }
        if (tid < 64) S->mrs[tid] = msrc[t * 64 + tid];
        __syncthreads();

        if (tid < 128) {
            // dots for rows rp, rp+32 and slots 2p, 2p+1
            const float4* qr  = (const float4*)&S->qp[p][0];
            const float4* xr0 = (const float4*)&S->xt[rp][0];
            const float4* xr1 = (const float4*)&S->xt[rp + 32][0];
            float2 a0[4] = {}, a1[4] = {};
#pragma unroll 16
            for (int c = 0; c < 64; c++) {
                float4 qA = qr[2 * c], qB = qr[2 * c + 1];   // elems 4c..4c+3 x 2 slots
                float4 xa = xr0[c], xb = xr1[c];
                ffma2(a0[0], make_float2(qA.x, qA.y), make_float2(xa.x, xa.x));
                ffma2(a0[1], make_float2(qA.z, qA.w), make_float2(xa.y, xa.y));
                ffma2(a0[2], make_float2(qB.x, qB.y), make_float2(xa.z, xa.z));
                ffma2(a0[3], make_float2(qB.z, qB.w), make_float2(xa.w, xa.w));
                ffma2(a1[0], make_float2(qA.x, qA.y), make_float2(xb.x, xb.x));
                ffma2(a1[1], make_float2(qA.z, qA.w), make_float2(xb.y, xb.y));
                ffma2(a1[2], make_float2(qB.x, qB.y), make_float2(xb.z, xb.z));
                ffma2(a1[3], make_float2(qB.z, qB.w), make_float2(xb.w, xb.w));
            }
            float2 mr0 = S->mrs[rp], mr1 = S->mrs[rp + 32];
            float2 d0 = make_float2((a0[0].x + a0[1].x) + (a0[2].x + a0[3].x),
                                    (a0[0].y + a0[1].y) + (a0[2].y + a0[3].y));
            float2 d1 = make_float2((a1[0].x + a1[1].x) + (a1[2].x + a1[3].x),
                                    (a1[0].y + a1[1].y) + (a1[2].y + a1[3].y));
            float dv00 = mr0.y * d0.x - mr0.x * qs1p.x + qbp.x;   // row rp,    slot 2p
            float dv01 = mr0.y * d0.y - mr0.x * qs1p.y + qbp.y;   // row rp,    slot 2p+1
            float dv10 = mr1.y * d1.x - mr1.x * qs1p.x + qbp.x;   // row rp+32, slot 2p
            float dv11 = mr1.y * d1.y - mr1.x * qs1p.y + qbp.y;   // row rp+32, slot 2p+1

            // softmax over 8 slots: lanes xor 1,2 share rp (p in lane bits 0..1)
            float m0 = fmaxf(dv00, dv01), m1 = fmaxf(dv10, dv11);
#pragma unroll
            for (int o = 1; o <= 2; o <<= 1) {
                m0 = fmaxf(m0, __shfl_xor_sync(0xffffffffu, m0, o));
                m1 = fmaxf(m1, __shfl_xor_sync(0xffffffffu, m1, o));
            }
            float e00 = expf(dv00 - m0), e01 = expf(dv01 - m0);
            float e10 = expf(dv10 - m1), e11 = expf(dv11 - m1);
            float sm0 = e00 + e01, sm1 = e10 + e11;
#pragma unroll
            for (int o = 1; o <= 2; o <<= 1) {
                sm0 += __shfl_xor_sync(0xffffffffu, sm0, o);
                sm1 += __shfl_xor_sync(0xffffffffu, sm1, o);
            }
            float a00 = e00 / sm0 + 1e-8f, a01 = e01 / sm0 + 1e-8f;
            float a10 = e10 / sm1 + 1e-8f, a11 = e11 / sm1 + 1e-8f;
            rs0 += a00 + a10;  rs1 += a01 + a11;
            s20 += a00 * mr0.x + a10 * mr1.x;
            s21 += a01 * mr0.x + a11 * mr1.x;
            S->at4[rp][2 * p]          = a00 * mr0.y;
            S->at4[rp][2 * p + 1]      = a01 * mr0.y;
            S->at4[rp + 32][2 * p]     = a10 * mr1.y;
            S->at4[rp + 32][2 * p + 1] = a11 * mr1.y;
        }
        __syncthreads();

        if (attn_out) {   // recover a = at4 / rs; coalesced over n
            int k2 = tid >> 5, n2 = tid & 31;
            size_t o = (size_t)(b * 8 + k2) * Nn + nb * 256 + t * 64;
            attn_out[o + n2]      = S->at4[n2][k2] / S->mrs[n2].y;
            attn_out[o + 32 + n2] = S->at4[n2 + 32][k2] / S->mrs[n2 + 32].y;
        }

        // agg: thread owns column e = tid; at4 rows broadcast
#pragma unroll 4
        for (int n = 0; n < 64; n++) {
            float xv = S->xt[n][tid];
            float2 xv2 = make_float2(xv, xv);
            const float4* ap = (const float4*)&S->at4[n][0];
            float4 aa = ap[0], ab = ap[1];
            ffma2(aggr[0], make_float2(aa.x, aa.y), xv2);
            ffma2(aggr[1], make_float2(aa.z, aa.w), xv2);
            ffma2(aggr[2], make_float2(ab.x, ab.y), xv2);
            ffma2(aggr[3], make_float2(ab.z, ab.w), xv2);
        }
        __syncthreads();
    }

    if (tid < 128) {
        S->rs_s[2 * p][rp]     = rs0;
        S->rs_s[2 * p + 1][rp] = rs1;
        S->s2_s[2 * p][rp]     = s20;
        S->s2_s[2 * p + 1][rp] = s21;
    }
    __syncthreads();
    if (tid < 8) {
        float s = 0.f, s2 = 0.f;
#pragma unroll
        for (int i = 0; i < 32; i++) { s += S->rs_s[tid][i]; s2 += S->s2_s[tid][i]; }
        g_rsp[(nb * Bz + b) * 8 + tid] = s;
        g_s2p[(nb * Bz + b) * 8 + tid] = s2;
    }
    size_t base = (size_t)(nb * Bz + b) * 8 * 256;
#pragma unroll
    for (int pp = 0; pp < 4; pp++) {
        g_aggp[base + (2 * pp)     * 256 + tid] = aggr[pp].x;
        g_aggp[base + (2 * pp + 1) * 256 + tid] = aggr[pp].y;
    }
}

// ---------------- fused: reduce -> upd -> GRU -> LN -> MLP -> next q' ------
struct FusedSmem {
    float ag[4][256], h[4][256], us[4][256], snew[4][256], sn[4][256];
    float p0[2][4][256], p1[2][4][256], p2[2][4][256], p3[2][4][256];
    float s1[4], s2[4], rinv[4];
};

__global__ void __launch_bounds__(512) k_fused(
    const float* __restrict__ b_ih, const float* __restrict__ b_hh,
    const float* __restrict__ b1, const float* __restrict__ b2,
    const float* __restrict__ lffg, const float* __restrict__ lffb,
    const float* __restrict__ lslg, const float* __restrict__ lslb,
    const float* __restrict__ ling, const float* __restrict__ linb,
    float* __restrict__ out_slots, int do_prep) {
    extern __shared__ char smem_raw[];
    FusedSmem* S = (FusedSmem*)smem_raw;
    int b = blockIdx.x, r0 = blockIdx.y * 4, tid = threadIdx.x;
    int j = tid & 255, hf = tid >> 8, kq0 = hf * 64;   // pair-index base
    int warp = tid >> 5, lane = tid & 31;

    // ---- stage a: reduce partials, load slots ----
    if (tid < 4) {
        float s1 = 0.f, s2 = 0.f;
#pragma unroll
        for (int nb = 0; nb < NB; nb++) {
            s1 += g_rsp[(nb * Bz + b) * 8 + r0 + tid];
            s2 += g_s2p[(nb * Bz + b) * 8 + r0 + tid];
        }
        S->s1[tid] = s1; S->s2[tid] = s2; S->rinv[tid] = 1.f / s1;
    }
#pragma unroll
    for (int i = 0; i < 2; i++) {
        int idx = tid + i * 512; int r = idx >> 8, e = idx & 255;
        float a = 0.f;
#pragma unroll
        for (int nb = 0; nb < NB; nb++)
            a += g_aggp[((size_t)(nb * Bz + b) * 8 + r0 + r) * 256 + e];
        S->ag[r][e] = a;
        S->h[r][e] = g_slots[(b * 8 + r0 + r) * 256 + e];
    }
    __syncthreads();
#pragma unroll
    for (int i = 0; i < 2; i++) {
        int idx = tid + i * 512; int r = idx >> 8, e = idx & 255;
        S->ag[r][e] = ling[e] * (S->ag[r][e] - S->s2[r]) + linb[e] * S->s1[r];
    }
    __syncthreads();

    // ---- stage b: us = (agg @ Wv^T) / rowsum ----
    {
        float2 acc2[4] = {};
#pragma unroll 8
        for (int kp = 0; kp < 64; kp++) {
            float2 w2 = g_WvT2[(size_t)(kq0 + kp) * 256 + j];
#pragma unroll
            for (int r = 0; r < 4; r++)
                ffma2(acc2[r], w2, *(const float2*)&S->ag[r][2 * (kq0 + kp)]);
        }
#pragma unroll
        for (int r = 0; r < 4; r++) S->p0[hf][r][j] = acc2[r].x + acc2[r].y;
    }
    __syncthreads();
#pragma unroll
    for (int i = 0; i < 2; i++) {
        int idx = tid + i * 512; int r = idx >> 8, e = idx & 255;
        S->us[r][e] = (S->p0[0][r][e] + S->p0[1][r][e]) * S->rinv[r];
    }
    __syncthreads();

    // ---- stage c: all three GRU gates in one k-pass ----
    {
        float2 racc[4] = {}, zacc[4] = {}, nai[4] = {}, nah[4] = {};
#pragma unroll 4
        for (int kp = 0; kp < 64; kp++) {
            const float2* wi = g_WihT2 + (size_t)(kq0 + kp) * 768;
            const float2* wh = g_WhhT2 + (size_t)(kq0 + kp) * 768;
            float2 wir = wi[j], wiz = wi[256 + j], win = wi[512 + j];
            float2 whr = wh[j], whz = wh[256 + j], whn = wh[512 + j];
#pragma unroll
            for (int r = 0; r < 4; r++) {
                float2 u2 = *(const float2*)&S->us[r][2 * (kq0 + kp)];
                float2 h2 = *(const float2*)&S->h[r][2 * (kq0 + kp)];
                ffma2(racc[r], wir, u2); ffma2(racc[r], whr, h2);
                ffma2(zacc[r], wiz, u2); ffma2(zacc[r], whz, h2);
                ffma2(nai[r],  win, u2); ffma2(nah[r],  whn, h2);
            }
        }
#pragma unroll
        for (int r = 0; r < 4; r++) {
            S->p0[hf][r][j] = racc[r].x + racc[r].y;
            S->p1[hf][r][j] = zacc[r].x + zacc[r].y;
            S->p2[hf][r][j] = nai[r].x + nai[r].y;
            S->p3[hf][r][j] = nah[r].x + nah[r].y;
        }
    }
    __syncthreads();
#pragma unroll
    for (int i = 0; i < 2; i++) {
        int idx = tid + i * 512; int r = idx >> 8, e = idx & 255;
        float rr = 1.f / (1.f + expf(-(S->p0[0][r][e] + S->p0[1][r][e] + b_ih[e] + b_hh[e])));
        float zz = 1.f / (1.f + expf(-(S->p1[0][r][e] + S->p1[1][r][e] + b_ih[256 + e] + b_hh[256 + e])));
        float nn = tanhf(S->p2[0][r][e] + S->p2[1][r][e] + b_ih[512 + e]
                         + rr * (S->p3[0][r][e] + S->p3[1][r][e] + b_hh[512 + e]));
        S->snew[r][e] = (1.f - zz) * nn + zz * S->h[r][e];
    }
    __syncthreads();

    // ---- stage d: LN(snew) -> sn ----
    if (warp < 4) ln_row(&S->snew[warp][0], &S->sn[warp][0], lffg, lffb, lane);
    __syncthreads();

    // ---- stage e: MLP1 (leaky relu) ----
    {
        float2 acc2[4] = {};
#pragma unroll 8
        for (int kp = 0; kp < 64; kp++) {
            float2 w2 = g_W1T2[(size_t)(kq0 + kp) * 256 + j];
#pragma unroll
            for (int r = 0; r < 4; r++)
                ffma2(acc2[r], w2, *(const float2*)&S->sn[r][2 * (kq0 + kp)]);
        }
#pragma unroll
        for (int r = 0; r < 4; r++) S->p0[hf][r][j] = acc2[r].x + acc2[r].y;
    }
    __syncthreads();
#pragma unroll
    for (int i = 0; i < 2; i++) {
        int idx = tid + i * 512; int r = idx >> 8, e = idx & 255;
        float t = S->p0[0][r][e] + S->p0[1][r][e] + b1[e];
        S->ag[r][e] = (t > 0.f) ? t : 0.01f * t;
    }
    __syncthreads();

    // ---- stage f: MLP2 + residual -> slots ----
    {
        float2 acc2[4] = {};
#pragma unroll 8
        for (int kp = 0; kp < 64; kp++) {
            float2 w2 = g_W2T2[(size_t)(kq0 + kp) * 256 + j];
#pragma unroll
            for (int r = 0; r < 4; r++)
                ffma2(acc2[r], w2, *(const float2*)&S->ag[r][2 * (kq0 + kp)]);
        }
#pragma unroll
        for (int r = 0; r < 4; r++) S->p0[hf][r][j] = acc2[r].x + acc2[r].y;
    }
    __syncthreads();
#pragma unroll
    for (int i = 0; i < 2; i++) {
        int idx = tid + i * 512; int r = idx >> 8, e = idx & 255;
        float o = S->snew[r][e] + S->p0[0][r][e] + S->p0[1][r][e] + b2[e];
        g_slots[(b * 8 + r0 + r) * 256 + e] = o;
        if (out_slots) out_slots[(b * 8 + r0 + r) * 256 + e] = o;
        S->h[r][e] = o;
    }
    __syncthreads();

    // ---- stage g: prep next iteration's qg / qs1 / qb ----
    if (do_prep) {
        if (warp < 4) ln_row(&S->h[warp][0], &S->sn[warp][0], lslg, lslb, lane);
        __syncthreads();
        {
            float2 acc2[4] = {};
#pragma unroll 8
            for (int kp = 0; kp < 64; kp++) {
                float2 w2 = g_wqk2p[(size_t)(kq0 + kp) * 256 + j];
#pragma unroll
                for (int r = 0; r < 4; r++)
                    ffma2(acc2[r], w2, *(const float2*)&S->sn[r][2 * (kq0 + kp)]);
            }
#pragma unroll
            for (int r = 0; r < 4; r++) S->p0[hf][r][j] = acc2[r].x + acc2[r].y;
        }
        __syncthreads();
#pragma unroll
        for (int i = 0; i < 2; i++) {
            int idx = tid + i * 512; int r = idx >> 8, e = idx & 255;
            float qp = S->p0[0][r][e] + S->p0[1][r][e];
            float qgv = 0.0625f * qp * ling[e];
            g_q[(b * 8 + r0 + r) * 256 + e] = qgv;
            S->us[r][e] = qgv;
            S->snew[r][e] = 0.0625f * qp * linb[e];
        }
        __syncthreads();
        if (warp < 4) {
            float s1v = 0.f, s2v = 0.f;
#pragma unroll
            for (int i = 0; i < 8; i++) {
                s1v += S->us[warp][lane + 32 * i];
                s2v += S->snew[warp][lane + 32 * i];
            }
            wred2(s1v, s2v);
            if (lane == 0) {
                g_qs1[b * 8 + r0 + warp] = s1v;
                g_qb[b * 8 + r0 + warp] = s2v;
            }
        }
    }
}

// ---------------- launch ------------------------------------------------------
extern "C" void kernel_launch(void* const* d_in, const int* in_sizes, int n_in,
                              void* d_out, int out_size) {
    const float* emb   = (const float*)d_in[0];
    const float* noise = (const float*)d_in[1];
    const float* mu    = (const float*)d_in[2];
    const float* ls    = (const float*)d_in[3];
    const float* Wq    = (const float*)d_in[4];
    const float* Wk    = (const float*)d_in[5];
    const float* Wv    = (const float*)d_in[6];
    const float* W_ih  = (const float*)d_in[7];
    const float* W_hh  = (const float*)d_in[8];
    const float* b_ih  = (const float*)d_in[9];
    const float* b_hh  = (const float*)d_in[10];
    const float* W1    = (const float*)d_in[11];
    const float* b1    = (const float*)d_in[12];
    const float* W2    = (const float*)d_in[13];
    const float* b2    = (const float*)d_in[14];
    const float* lin_g = (const float*)d_in[15];
    const float* lin_b = (const float*)d_in[16];
    const float* lsl_g = (const float*)d_in[17];
    const float* lsl_b = (const float*)d_in[18];
    const float* lff_g = (const float*)d_in[19];
    const float* lff_b = (const float*)d_in[20];

    float* out       = (float*)d_out;
    float* out_slots = out;                  // [B,K,D]
    float* out_attn  = out + Bz * Kk * Dd;   // [B,K,N]

    cudaFuncSetAttribute(k_attn, cudaFuncAttributeMaxDynamicSharedMemorySize,
                         (int)sizeof(AttnSmem));
    cudaFuncSetAttribute(k_fused, cudaFuncAttributeMaxDynamicSharedMemorySize,
                         (int)sizeof(FusedSmem));

    k_setup<<<RS_BLOCKS + INIT_BLOCKS + 576, 256>>>(
        emb, noise, mu, ls, Wv, W_ih, W_hh, W1, W2);
    k_wqk<<<dim3(8, 8), 256>>>(Wq, Wk);
    k_prep0<<<Bz, 256>>>(lsl_g, lsl_b, lin_g, lin_b);

    for (int it = 0; it < 3; it++) {
        k_attn<<<dim3(NB, Bz), 256, sizeof(AttnSmem)>>>(
            emb, (it == 2) ? out_attn : nullptr);
        k_fused<<<dim3(Bz, 2), 512, sizeof(FusedSmem)>>>(
            b_ih, b_hh, b1, b2, lff_g, lff_b, lsl_g, lsl_b, lin_g, lin_b,
            (it == 2) ? out_slots : nullptr, (it < 2) ? 1 : 0);
    }
}